// round 9
// baseline (speedup 1.0000x reference)
#include <cuda_runtime.h>
#include <cuda_bf16.h>
#include <mma.h>
#include <math.h>
#include <stdint.h>

using namespace nvcuda;

#define N_RAYS   32768
#define N_PLANES 32
#define NSAMP    (N_RAYS * N_PLANES)
#define EPSV     1e-8f
#define BM       64
#define PERSIST_BLOCKS 148
#define THREADS  512

// ---------------- scratch ----------------
__device__ int   g_cnt;
__device__ int   g_sidx[NSAMP];
__device__ float g_world[NSAMP * 3];
__device__ float g_vd[NSAMP * 3];
__device__ float g_t[NSAMP];
__device__ float g_rgba[NSAMP * 4];

// ---------------- kernel 0 ----------------
__global__ void k_reset() { if (threadIdx.x == 0) g_cnt = 0; }

// ---------------- kernel 1: geometry + compaction ----------------
__global__ void __launch_bounds__(256) k_geom(
    const float* __restrict__ ndc, const float* __restrict__ cam_pos,
    const float* __restrict__ cam_R, const float* __restrict__ basis,
    const float* __restrict__ center, const float* __restrict__ wh)
{
    int gid = blockIdx.x * blockDim.x + threadIdx.x;
    if (gid >= NSAMP) return;
    int p = gid / N_RAYS;
    int n = gid - p * N_RAYS;

    float nd0 = ndc[n * 3 + 0], nd1 = ndc[n * 3 + 1], nd2 = ndc[n * 3 + 2];
    float d0 = cam_R[0] * nd0 + cam_R[1] * nd1 + cam_R[2] * nd2;
    float d1 = cam_R[3] * nd0 + cam_R[4] * nd1 + cam_R[5] * nd2;
    float d2 = cam_R[6] * nd0 + cam_R[7] * nd1 + cam_R[8] * nd2;
    float o0 = cam_pos[0], o1 = cam_pos[1], o2 = cam_pos[2];

    const float* B = basis + p * 9;
    float pn0 = B[2], pn1 = B[5], pn2 = B[8];
    float c0 = center[p * 3 + 0], c1 = center[p * 3 + 1], c2 = center[p * 3 + 2];

    float denom = pn0 * d0 + pn1 * d1 + pn2 * d2;
    if (fabsf(denom) < EPSV) denom = EPSV;
    float num = (c0 - o0) * pn0 + (c1 - o1) * pn1 + (c2 - o2) * pn2;
    float t = num / denom;

    float w0 = o0 + t * d0, w1 = o1 + t * d1, w2 = o2 + t * d2;
    float u = (w0 - c0) * B[0] + (w1 - c1) * B[3] + (w2 - c2) * B[6];
    float v = (w0 - c0) * B[1] + (w1 - c1) * B[4] + (w2 - c2) * B[7];
    bool inside = (fabsf(u) <= wh[p * 2 + 0] * 0.5f) && (fabsf(v) <= wh[p * 2 + 1] * 0.5f);
    bool hit = inside && (t > 0.0f);

    g_t[gid] = t;

    unsigned mask = __ballot_sync(0xffffffffu, hit);
    if (hit) {
        int lane   = threadIdx.x & 31;
        int leader = __ffs(mask) - 1;
        int rank   = __popc(mask & ((1u << lane) - 1u));
        int base   = 0;
        if (lane == leader) base = atomicAdd(&g_cnt, __popc(mask));
        base = __shfl_sync(mask, base, leader);
        int i = base + rank;
        g_sidx[i] = gid;
        g_world[i * 3 + 0] = w0;
        g_world[i * 3 + 1] = w1;
        g_world[i * 3 + 2] = w2;
        float vd0 = w0 - o0, vd1 = w1 - o1, vd2 = w2 - o2;
        float inv = 1.0f / (sqrtf(vd0 * vd0 + vd1 * vd1 + vd2 * vd2) + EPSV);
        g_vd[i * 3 + 0] = vd0 * inv;
        g_vd[i * 3 + 1] = vd1 * inv;
        g_vd[i * 3 + 2] = vd2 * inv;
    } else {
        float4 z = make_float4(0.f, 0.f, 0.f, 0.f);
        *reinterpret_cast<float4*>(&g_rgba[gid * 4]) = z;
    }
}

// ---------------- fused persistent WMMA MLP ----------------
#define LDW  136   // W0/W1 (N=128 + pad)
#define LDWC 72    // Wc1  (N=64 + pad)
#define LDA  168   // activations (K up to 160 + pad)
#define LDC  132   // fp32 C scratch

#define SM_W0H   0
#define SM_W0L   (SM_W0H  + 64  * LDW  * 2)
#define SM_W1H   (SM_W0L  + 64  * LDW  * 2)
#define SM_W1L   (SM_W1H  + 128 * LDW  * 2)
#define SM_WC1H  (SM_W1L  + 128 * LDW  * 2)
#define SM_WC1L  (SM_WC1H + 160 * LDWC * 2)
#define SM_AH    (SM_WC1L + 160 * LDWC * 2)
#define SM_AL    (SM_AH   + 64  * LDA  * 2)
#define SM_C     (SM_AL   + 64  * LDA  * 2)
#define SM_SMALL (SM_C    + 64  * LDC  * 4)
#define SF_B0   0
#define SF_B1   128
#define SF_WA   256
#define SF_WC2  384
#define SF_BC1  576
#define SF_ALPHA 640
#define SF_END  704
#define SMEM_BYTES (SM_SMALL + SF_END * 4)    // 230144

typedef __nv_bfloat16 bf16;

__device__ __forceinline__ void split_bf16(float w, bf16& h, bf16& l) {
    h = __float2bfloat16(w);
    l = __float2bfloat16(w - __bfloat162float(h));
}

__device__ void stage_weight(const float* __restrict__ W, char* smem,
                             int hoff, int loff, int N, int Ksrc, int Kpad, int ld, int tid)
{
    for (int idx = tid; idx < Kpad * N; idx += THREADS) {
        int k = idx / N;
        int n = idx - k * N;
        float w = (k < Ksrc) ? W[k * N + n] : 0.0f;
        bf16 h, l; split_bf16(w, h, l);
        reinterpret_cast<bf16*>(smem + hoff)[k * ld + n] = h;
        reinterpret_cast<bf16*>(smem + loff)[k * ld + n] = l;
    }
}

// C[16 x NFRAG*16] = A[16 x K] @ B[K x NFRAG*16] with 2-term split (3 MMAs)
template <int KSTEPS, int NFRAG, int LDB>
__device__ __forceinline__ void wmma_layer(
    const bf16* Ah, const bf16* Al, const bf16* Bh, const bf16* Bl,
    float* C, int r16, int cb)
{
    wmma::fragment<wmma::accumulator, 16, 16, 16, float> acc[NFRAG];
    #pragma unroll
    for (int j = 0; j < NFRAG; j++) wmma::fill_fragment(acc[j], 0.0f);

    #pragma unroll
    for (int ks = 0; ks < KSTEPS; ks++) {
        wmma::fragment<wmma::matrix_a, 16, 16, 16, bf16, wmma::row_major> ah, al;
        wmma::load_matrix_sync(ah, Ah + r16 * LDA + ks * 16, LDA);
        wmma::load_matrix_sync(al, Al + r16 * LDA + ks * 16, LDA);
        #pragma unroll
        for (int j = 0; j < NFRAG; j++) {
            wmma::fragment<wmma::matrix_b, 16, 16, 16, bf16, wmma::row_major> bh, bl;
            wmma::load_matrix_sync(bh, Bh + ks * 16 * LDB + cb + j * 16, LDB);
            wmma::load_matrix_sync(bl, Bl + ks * 16 * LDB + cb + j * 16, LDB);
            wmma::mma_sync(acc[j], ah, bh, acc[j]);
            wmma::mma_sync(acc[j], ah, bl, acc[j]);
            wmma::mma_sync(acc[j], al, bh, acc[j]);
        }
    }
    #pragma unroll
    for (int j = 0; j < NFRAG; j++)
        wmma::store_matrix_sync(C + r16 * LDC + cb + j * 16, acc[j], LDC, wmma::mem_row_major);
}

__global__ void __launch_bounds__(THREADS, 1) k_mlp(
    const float* __restrict__ W0,  const float* __restrict__ b0,
    const float* __restrict__ W1,  const float* __restrict__ b1,
    const float* __restrict__ Wa,  const float* __restrict__ ba,
    const float* __restrict__ Wc1, const float* __restrict__ bc1,
    const float* __restrict__ Wc2, const float* __restrict__ bc2)
{
    extern __shared__ char smem[];
    bf16* W0h  = reinterpret_cast<bf16*>(smem + SM_W0H);
    bf16* W0l  = reinterpret_cast<bf16*>(smem + SM_W0L);
    bf16* W1h  = reinterpret_cast<bf16*>(smem + SM_W1H);
    bf16* W1l  = reinterpret_cast<bf16*>(smem + SM_W1L);
    bf16* Wc1h = reinterpret_cast<bf16*>(smem + SM_WC1H);
    bf16* Wc1l = reinterpret_cast<bf16*>(smem + SM_WC1L);
    bf16* Ah   = reinterpret_cast<bf16*>(smem + SM_AH);
    bf16* Al   = reinterpret_cast<bf16*>(smem + SM_AL);
    float* Cs  = reinterpret_cast<float*>(smem + SM_C);
    float* smf = reinterpret_cast<float*>(smem + SM_SMALL);
    float* bias0 = smf + SF_B0;
    float* bias1 = smf + SF_B1;
    float* Was   = smf + SF_WA;
    float* Wc2s  = smf + SF_WC2;
    float* bc1s  = smf + SF_BC1;
    float* alpha = smf + SF_ALPHA;

    const int tid  = threadIdx.x;
    const int wid  = tid >> 5;        // 0..15
    const int r    = tid >> 3;        // sample row 0..63 (8 threads/row)
    const int o    = tid & 7;         // octant within row
    const int r16  = (wid >> 2) * 16; // warp row stripe
    const int cb32 = (wid & 3) * 32;  // warp col block (N=128 layers)
    const int cb16 = (wid & 3) * 16;  // warp col block (N=64 layer)
    const float ba0  = ba[0];
    const float bc20 = bc2[0], bc21 = bc2[1], bc22 = bc2[2];
    const bf16 bz = __float2bfloat16(0.f);

    // ---- one-time weight staging ----
    stage_weight(W0,  smem, SM_W0H,  SM_W0L,  128, 60,  64,  LDW,  tid);
    stage_weight(W1,  smem, SM_W1H,  SM_W1L,  128, 128, 128, LDW,  tid);
    stage_weight(Wc1, smem, SM_WC1H, SM_WC1L, 64,  152, 160, LDWC, tid);
    if (tid < 128) { bias0[tid] = b0[tid]; bias1[tid] = b1[tid]; Was[tid] = Wa[tid]; }
    if (tid >= 128 && tid < 320) Wc2s[tid - 128] = Wc2[tid - 128];
    if (tid >= 320 && tid < 384) bc1s[tid - 320] = bc1[tid - 320];
    __syncthreads();

    const int cnt    = g_cnt;
    const int nTiles = (cnt + BM - 1) >> 6;

    for (int tile = blockIdx.x; tile < nTiles; tile += gridDim.x) {
        const int gi   = (tile << 6) + r;
        const bool live = gi < cnt;

        // ===== S1: positional encoding -> Ah/Al (cols 0..63), 8 threads/sample =====
        {
            bf16* rh = Ah + r * LDA;
            bf16* rl = Al + r * LDA;
            if (live) {
                const float* wp = &g_world[gi * 3];
                float x0 = wp[0], x1 = wp[1], x2 = wp[2];
                for (int u = o; u < 30; u += 8) {
                    int c = (u >= 20) ? 2 : (u >= 10 ? 1 : 0);
                    int j = u - c * 10;
                    float x = (c == 0) ? x0 : (c == 1 ? x1 : x2);
                    float s, co;
                    sincosf(x * (float)(1 << j), &s, &co);
                    bf16 h, l;
                    split_bf16(s, h, l);  rh[c * 20 + j] = h;      rl[c * 20 + j] = l;
                    split_bf16(co, h, l); rh[c * 20 + 10 + j] = h; rl[c * 20 + 10 + j] = l;
                }
            } else {
                for (int u = o; u < 30; u += 8) {
                    int c = (u >= 20) ? 2 : (u >= 10 ? 1 : 0);
                    int j = u - c * 10;
                    rh[c * 20 + j] = bz;      rl[c * 20 + j] = bz;
                    rh[c * 20 + 10 + j] = bz; rl[c * 20 + 10 + j] = bz;
                }
            }
            if (o < 4) { rh[60 + o] = bz; rl[60 + o] = bz; }   // pad 60..63
        }
        __syncthreads();

        // ===== L0: C = enc @ W0 (K=64, N=128) =====
        wmma_layer<4, 2, LDW>(Ah, Al, W0h, W0l, Cs, r16, cb32);
        __syncthreads();

        // ===== L0 epilogue: h0 = relu(C + b0) -> Ah/Al cols 0..127 (16 cols/thread) =====
        {
            const float* crow = Cs + r * LDC;
            bf16* rh = Ah + r * LDA;
            bf16* rl = Al + r * LDA;
            int c0i = o * 16;
            #pragma unroll
            for (int c = 0; c < 16; c++) {
                float v = crow[c0i + c] + bias0[c0i + c];
                v = v > 0.f ? v : 0.f;
                bf16 h, l; split_bf16(v, h, l);
                rh[c0i + c] = h; rl[c0i + c] = l;
            }
        }
        __syncthreads();

        // ===== L1: C = h0 @ W1 (K=128, N=128) =====
        wmma_layer<8, 2, LDW>(Ah, Al, W1h, W1l, Cs, r16, cb32);
        __syncthreads();

        // ===== L1 epilogue: h1 = relu(C + b1); alpha; denc =====
        {
            const float* crow = Cs + r * LDC;
            bf16* rh = Ah + r * LDA;
            bf16* rl = Al + r * LDA;
            int c0i = o * 16;
            float aacc = 0.f;
            #pragma unroll
            for (int c = 0; c < 16; c++) {
                float v = crow[c0i + c] + bias1[c0i + c];
                v = v > 0.f ? v : 0.f;
                aacc = fmaf(v, Was[c0i + c], aacc);
                bf16 h, l; split_bf16(v, h, l);
                rh[c0i + c] = h; rl[c0i + c] = l;
            }
            aacc += __shfl_xor_sync(0xffffffffu, aacc, 1);
            aacc += __shfl_xor_sync(0xffffffffu, aacc, 2);
            aacc += __shfl_xor_sync(0xffffffffu, aacc, 4);
            if (o == 0) alpha[r] = 1.0f / (1.0f + expf(-(aacc + ba0)));

            // direction encoding -> cols 128..151, pad 152..159
            if (live) {
                const float* vp = &g_vd[gi * 3];
                float x0 = vp[0], x1 = vp[1], x2 = vp[2];
                for (int u = o; u < 12; u += 8) {
                    int c = u >> 2, j = u & 3;
                    float x = (c == 0) ? x0 : (c == 1 ? x1 : x2);
                    float s, co;
                    sincosf(x * (float)(1 << j), &s, &co);
                    bf16 h, l;
                    split_bf16(s, h, l);  rh[128 + c * 8 + j] = h;     rl[128 + c * 8 + j] = l;
                    split_bf16(co, h, l); rh[128 + c * 8 + 4 + j] = h; rl[128 + c * 8 + 4 + j] = l;
                }
            } else {
                for (int u = o; u < 12; u += 8) {
                    int c = u >> 2, j = u & 3;
                    rh[128 + c * 8 + j] = bz;     rl[128 + c * 8 + j] = bz;
                    rh[128 + c * 8 + 4 + j] = bz; rl[128 + c * 8 + 4 + j] = bz;
                }
            }
            rh[152 + o] = bz; rl[152 + o] = bz;   // pad 152..159 (one col per thread)
        }
        __syncthreads();

        // ===== Wc1: C = [h1 | denc] @ Wc1 (K=160, N=64) =====
        wmma_layer<10, 1, LDWC>(Ah, Al, Wc1h, Wc1l, Cs, r16, cb16);
        __syncthreads();

        // ===== final: hc = relu(C + bc1); rgb = sigmoid(hc @ Wc2 + bc2); scatter =====
        {
            const float* crow = Cs + r * LDC;
            int c0i = o * 8;
            float a0 = 0.f, a1 = 0.f, a2 = 0.f;
            #pragma unroll
            for (int c = 0; c < 8; c++) {
                float h = crow[c0i + c] + bc1s[c0i + c];
                h = h > 0.f ? h : 0.f;
                a0 = fmaf(h, Wc2s[(c0i + c) * 3 + 0], a0);
                a1 = fmaf(h, Wc2s[(c0i + c) * 3 + 1], a1);
                a2 = fmaf(h, Wc2s[(c0i + c) * 3 + 2], a2);
            }
            a0 += __shfl_xor_sync(0xffffffffu, a0, 1);
            a0 += __shfl_xor_sync(0xffffffffu, a0, 2);
            a0 += __shfl_xor_sync(0xffffffffu, a0, 4);
            a1 += __shfl_xor_sync(0xffffffffu, a1, 1);
            a1 += __shfl_xor_sync(0xffffffffu, a1, 2);
            a1 += __shfl_xor_sync(0xffffffffu, a1, 4);
            a2 += __shfl_xor_sync(0xffffffffu, a2, 1);
            a2 += __shfl_xor_sync(0xffffffffu, a2, 2);
            a2 += __shfl_xor_sync(0xffffffffu, a2, 4);
            if (o == 0 && live) {
                float4 outv;
                outv.x = 1.0f / (1.0f + expf(-(a0 + bc20)));
                outv.y = 1.0f / (1.0f + expf(-(a1 + bc21)));
                outv.z = 1.0f / (1.0f + expf(-(a2 + bc22)));
                outv.w = alpha[r];
                *reinterpret_cast<float4*>(&g_rgba[g_sidx[gi] * 4]) = outv;
            }
        }
        __syncthreads();
    }
}

// ---------------- kernel 5: composite (register bitonic sort) ----------------
__global__ void __launch_bounds__(128) k_composite(float* __restrict__ out)
{
    int n = blockIdx.x * blockDim.x + threadIdx.x;
    if (n >= N_RAYS) return;

    float tv[N_PLANES];
    int   pv[N_PLANES];
    #pragma unroll
    for (int p = 0; p < N_PLANES; p++) {
        tv[p] = g_t[p * N_RAYS + n];
        pv[p] = p;
    }

    #pragma unroll
    for (int k = 2; k <= N_PLANES; k <<= 1) {
        #pragma unroll
        for (int j = k >> 1; j > 0; j >>= 1) {
            #pragma unroll
            for (int i = 0; i < N_PLANES; i++) {
                int l = i ^ j;
                if (l > i) {
                    bool up = ((i & k) == 0);
                    bool sw = up ? (tv[i] > tv[l]) : (tv[i] < tv[l]);
                    if (sw) {
                        float tt = tv[i]; tv[i] = tv[l]; tv[l] = tt;
                        int   pp = pv[i]; pv[i] = pv[l]; pv[l] = pp;
                    }
                }
            }
        }
    }

    float trans = 1.0f, sw = 0.0f, depth = 0.0f;
    float c0 = 0.f, c1 = 0.f, c2 = 0.f;
    #pragma unroll
    for (int s = 0; s < N_PLANES; s++) {
        int p = pv[s];
        float4 rg = *reinterpret_cast<const float4*>(&g_rgba[(p * N_RAYS + n) * 4]);
        float a = rg.w;
        float w = a * trans;
        depth = fmaf(tv[s], w, depth);
        c0 = fmaf(rg.x, w, c0);
        c1 = fmaf(rg.y, w, c1);
        c2 = fmaf(rg.z, w, c2);
        sw += w;
        trans *= (1.0f - a);
    }
    float bg = 1.0f - sw;
    out[n * 4 + 0] = c0 + bg;
    out[n * 4 + 1] = c1 + bg;
    out[n * 4 + 2] = c2 + bg;
    out[n * 4 + 3] = depth;
}

// ---------------- launch ----------------
extern "C" void kernel_launch(void* const* d_in, const int* in_sizes, int n_in,
                              void* d_out, int out_size)
{
    const float* ndc    = (const float*)d_in[0];
    const float* campos = (const float*)d_in[1];
    const float* camR   = (const float*)d_in[2];
    const float* basis  = (const float*)d_in[3];
    const float* center = (const float*)d_in[4];
    const float* wh     = (const float*)d_in[5];
    const float* W0     = (const float*)d_in[6];
    const float* b0     = (const float*)d_in[7];
    const float* W1     = (const float*)d_in[8];
    const float* b1     = (const float*)d_in[9];
    const float* Wa     = (const float*)d_in[10];
    const float* ba     = (const float*)d_in[11];
    const float* Wc1    = (const float*)d_in[12];
    const float* bc1    = (const float*)d_in[13];
    const float* Wc2    = (const float*)d_in[14];
    const float* bc2    = (const float*)d_in[15];
    float* out = (float*)d_out;

    static int smem_set = 0;
    if (!smem_set) {
        cudaFuncSetAttribute(k_mlp, cudaFuncAttributeMaxDynamicSharedMemorySize, SMEM_BYTES);
        smem_set = 1;
    }

    k_reset<<<1, 32>>>();
    k_geom<<<NSAMP / 256, 256>>>(ndc, campos, camR, basis, center, wh);
    k_mlp<<<PERSIST_BLOCKS, THREADS, SMEM_BYTES>>>(W0, b0, W1, b1, Wa, ba, Wc1, bc1, Wc2, bc2);
    k_composite<<<(N_RAYS + 127) / 128, 128>>>(out);
}

// round 10
// speedup vs baseline: 1.2746x; 1.2746x over previous
#include <cuda_runtime.h>
#include <cuda_bf16.h>
#include <mma.h>
#include <math.h>
#include <stdint.h>

using namespace nvcuda;

#define N_RAYS   32768
#define N_PLANES 32
#define NSAMP    (N_RAYS * N_PLANES)
#define EPSV     1e-8f
#define BM       32          // rows per half-tile
#define PERSIST_BLOCKS 148
#define THREADS  256

// ---------------- scratch ----------------
__device__ int   g_cnt;
__device__ int   g_sidx[NSAMP];
__device__ float g_world[NSAMP * 3];
__device__ float g_vd[NSAMP * 3];
__device__ float g_t[NSAMP];
__device__ float g_rgba[NSAMP * 4];

// ---------------- kernel 0 ----------------
__global__ void k_reset() { if (threadIdx.x == 0) g_cnt = 0; }

// ---------------- kernel 1: geometry + compaction ----------------
__global__ void __launch_bounds__(256) k_geom(
    const float* __restrict__ ndc, const float* __restrict__ cam_pos,
    const float* __restrict__ cam_R, const float* __restrict__ basis,
    const float* __restrict__ center, const float* __restrict__ wh)
{
    int gid = blockIdx.x * blockDim.x + threadIdx.x;
    if (gid >= NSAMP) return;
    int p = gid / N_RAYS;
    int n = gid - p * N_RAYS;

    float nd0 = ndc[n * 3 + 0], nd1 = ndc[n * 3 + 1], nd2 = ndc[n * 3 + 2];
    float d0 = cam_R[0] * nd0 + cam_R[1] * nd1 + cam_R[2] * nd2;
    float d1 = cam_R[3] * nd0 + cam_R[4] * nd1 + cam_R[5] * nd2;
    float d2 = cam_R[6] * nd0 + cam_R[7] * nd1 + cam_R[8] * nd2;
    float o0 = cam_pos[0], o1 = cam_pos[1], o2 = cam_pos[2];

    const float* B = basis + p * 9;
    float pn0 = B[2], pn1 = B[5], pn2 = B[8];
    float c0 = center[p * 3 + 0], c1 = center[p * 3 + 1], c2 = center[p * 3 + 2];

    float denom = pn0 * d0 + pn1 * d1 + pn2 * d2;
    if (fabsf(denom) < EPSV) denom = EPSV;
    float num = (c0 - o0) * pn0 + (c1 - o1) * pn1 + (c2 - o2) * pn2;
    float t = num / denom;

    float w0 = o0 + t * d0, w1 = o1 + t * d1, w2 = o2 + t * d2;
    float u = (w0 - c0) * B[0] + (w1 - c1) * B[3] + (w2 - c2) * B[6];
    float v = (w0 - c0) * B[1] + (w1 - c1) * B[4] + (w2 - c2) * B[7];
    bool inside = (fabsf(u) <= wh[p * 2 + 0] * 0.5f) && (fabsf(v) <= wh[p * 2 + 1] * 0.5f);
    bool hit = inside && (t > 0.0f);

    g_t[gid] = t;

    unsigned mask = __ballot_sync(0xffffffffu, hit);
    if (hit) {
        int lane   = threadIdx.x & 31;
        int leader = __ffs(mask) - 1;
        int rank   = __popc(mask & ((1u << lane) - 1u));
        int base   = 0;
        if (lane == leader) base = atomicAdd(&g_cnt, __popc(mask));
        base = __shfl_sync(mask, base, leader);
        int i = base + rank;
        g_sidx[i] = gid;
        g_world[i * 3 + 0] = w0;
        g_world[i * 3 + 1] = w1;
        g_world[i * 3 + 2] = w2;
        float vd0 = w0 - o0, vd1 = w1 - o1, vd2 = w2 - o2;
        float inv = 1.0f / (sqrtf(vd0 * vd0 + vd1 * vd1 + vd2 * vd2) + EPSV);
        g_vd[i * 3 + 0] = vd0 * inv;
        g_vd[i * 3 + 1] = vd1 * inv;
        g_vd[i * 3 + 2] = vd2 * inv;
    } else {
        float4 z = make_float4(0.f, 0.f, 0.f, 0.f);
        *reinterpret_cast<float4*>(&g_rgba[gid * 4]) = z;
    }
}

// ---------------- fused persistent WMMA MLP (dual half-tiles) ----------------
#define LDW  136
#define LDWC 72
#define LDA  168
#define LDC  132

#define A_HALF_B (BM * LDA * 2)    // 10752
#define C_HALF_B (BM * LDC * 4)    // 16896

#define SM_W0H   0
#define SM_W0L   (SM_W0H  + 64  * LDW  * 2)
#define SM_W1H   (SM_W0L  + 64  * LDW  * 2)
#define SM_W1L   (SM_W1H  + 128 * LDW  * 2)
#define SM_WC1H  (SM_W1L  + 128 * LDW  * 2)
#define SM_WC1L  (SM_WC1H + 160 * LDWC * 2)
#define SM_AH    (SM_WC1L + 160 * LDWC * 2)        // 150528, 2 halves
#define SM_AL    (SM_AH   + 2 * A_HALF_B)
#define SM_C     (SM_AL   + 2 * A_HALF_B)
#define SM_SMALL (SM_C    + 2 * C_HALF_B)
#define SF_B0   0
#define SF_B1   128
#define SF_WA   256
#define SF_WC2  384
#define SF_BC1  576
#define SF_ALPHA 640
#define SF_END  704
#define SMEM_BYTES (SM_SMALL + SF_END * 4)         // 230144

typedef __nv_bfloat16 bf16;

#define HBAR(id) asm volatile("bar.sync %0, %1;" :: "r"(id), "r"(128) : "memory")

__device__ __forceinline__ void split_bf16(float w, bf16& h, bf16& l) {
    h = __float2bfloat16(w);
    l = __float2bfloat16(w - __bfloat162float(h));
}

__device__ void stage_weight(const float* __restrict__ W, char* smem,
                             int hoff, int loff, int N, int Ksrc, int Kpad, int ld, int tid)
{
    for (int idx = tid; idx < Kpad * N; idx += THREADS) {
        int k = idx / N;
        int n = idx - k * N;
        float w = (k < Ksrc) ? W[k * N + n] : 0.0f;
        bf16 h, l; split_bf16(w, h, l);
        reinterpret_cast<bf16*>(smem + hoff)[k * ld + n] = h;
        reinterpret_cast<bf16*>(smem + loff)[k * ld + n] = l;
    }
}

template <int KSTEPS, int NFRAG, int LDB>
__device__ __forceinline__ void wmma_layer(
    const bf16* Ah, const bf16* Al, const bf16* Bh, const bf16* Bl,
    float* C, int r16, int cb)
{
    wmma::fragment<wmma::accumulator, 16, 16, 16, float> acc[NFRAG];
    #pragma unroll
    for (int j = 0; j < NFRAG; j++) wmma::fill_fragment(acc[j], 0.0f);

    #pragma unroll
    for (int ks = 0; ks < KSTEPS; ks++) {
        wmma::fragment<wmma::matrix_a, 16, 16, 16, bf16, wmma::row_major> ah, al;
        wmma::load_matrix_sync(ah, Ah + r16 * LDA + ks * 16, LDA);
        wmma::load_matrix_sync(al, Al + r16 * LDA + ks * 16, LDA);
        #pragma unroll
        for (int j = 0; j < NFRAG; j++) {
            wmma::fragment<wmma::matrix_b, 16, 16, 16, bf16, wmma::row_major> bh, bl;
            wmma::load_matrix_sync(bh, Bh + ks * 16 * LDB + cb + j * 16, LDB);
            wmma::load_matrix_sync(bl, Bl + ks * 16 * LDB + cb + j * 16, LDB);
            wmma::mma_sync(acc[j], ah, bh, acc[j]);
            wmma::mma_sync(acc[j], ah, bl, acc[j]);
            wmma::mma_sync(acc[j], al, bh, acc[j]);
        }
    }
    #pragma unroll
    for (int j = 0; j < NFRAG; j++)
        wmma::store_matrix_sync(C + r16 * LDC + cb + j * 16, acc[j], LDC, wmma::mem_row_major);
}

// bias+relu+split 4 cols: float4 in, paired bf16 out
__device__ __forceinline__ void epi4(const float4 cv, const float4 bv,
                                     bf16* rh, bf16* rl, int c)
{
    float v0 = cv.x + bv.x; v0 = v0 > 0.f ? v0 : 0.f;
    float v1 = cv.y + bv.y; v1 = v1 > 0.f ? v1 : 0.f;
    float v2 = cv.z + bv.z; v2 = v2 > 0.f ? v2 : 0.f;
    float v3 = cv.w + bv.w; v3 = v3 > 0.f ? v3 : 0.f;
    __nv_bfloat162 h01 = __floats2bfloat162_rn(v0, v1);
    __nv_bfloat162 h23 = __floats2bfloat162_rn(v2, v3);
    __nv_bfloat162 l01 = __floats2bfloat162_rn(v0 - __low2float(h01), v1 - __high2float(h01));
    __nv_bfloat162 l23 = __floats2bfloat162_rn(v2 - __low2float(h23), v3 - __high2float(h23));
    *reinterpret_cast<__nv_bfloat162*>(rh + c)     = h01;
    *reinterpret_cast<__nv_bfloat162*>(rh + c + 2) = h23;
    *reinterpret_cast<__nv_bfloat162*>(rl + c)     = l01;
    *reinterpret_cast<__nv_bfloat162*>(rl + c + 2) = l23;
}

__global__ void __launch_bounds__(THREADS, 1) k_mlp(
    const float* __restrict__ W0,  const float* __restrict__ b0,
    const float* __restrict__ W1,  const float* __restrict__ b1,
    const float* __restrict__ Wa,  const float* __restrict__ ba,
    const float* __restrict__ Wc1, const float* __restrict__ bc1,
    const float* __restrict__ Wc2, const float* __restrict__ bc2)
{
    extern __shared__ char smem[];
    bf16* W0h  = reinterpret_cast<bf16*>(smem + SM_W0H);
    bf16* W0l  = reinterpret_cast<bf16*>(smem + SM_W0L);
    bf16* W1h  = reinterpret_cast<bf16*>(smem + SM_W1H);
    bf16* W1l  = reinterpret_cast<bf16*>(smem + SM_W1L);
    bf16* Wc1h = reinterpret_cast<bf16*>(smem + SM_WC1H);
    bf16* Wc1l = reinterpret_cast<bf16*>(smem + SM_WC1L);
    float* smf = reinterpret_cast<float*>(smem + SM_SMALL);
    float* bias0 = smf + SF_B0;
    float* bias1 = smf + SF_B1;
    float* Was   = smf + SF_WA;
    float* Wc2s  = smf + SF_WC2;
    float* bc1s  = smf + SF_BC1;
    float* alpha = smf + SF_ALPHA;

    const int tid  = threadIdx.x;
    const int half = tid >> 7;            // 0 / 1
    const int ht   = tid & 127;           // thread within half
    const int hw   = (ht >> 5);           // warp within half 0..3
    const int r16  = (hw >> 1) * 16;      // row stripe
    const int cb64 = (hw & 1) * 64;       // col block, N=128
    const int cb32 = (hw & 1) * 32;       // col block, N=64
    const int r    = ht >> 2;             // sample row 0..31
    const int q    = ht & 3;              // 4 threads per row
    const int barid = half + 1;

    bf16* Ah = reinterpret_cast<bf16*>(smem + SM_AH + half * A_HALF_B);
    bf16* Al = reinterpret_cast<bf16*>(smem + SM_AL + half * A_HALF_B);
    float* Cs = reinterpret_cast<float*>(smem + SM_C + half * C_HALF_B);
    float* alph = alpha + half * 32;

    const float ba0  = ba[0];
    const float bc20 = bc2[0], bc21 = bc2[1], bc22 = bc2[2];
    const bf16 bz = __float2bfloat16(0.f);

    // ---- one-time weight staging ----
    stage_weight(W0,  smem, SM_W0H,  SM_W0L,  128, 60,  64,  LDW,  tid);
    stage_weight(W1,  smem, SM_W1H,  SM_W1L,  128, 128, 128, LDW,  tid);
    stage_weight(Wc1, smem, SM_WC1H, SM_WC1L, 64,  152, 160, LDWC, tid);
    if (tid < 128) { bias0[tid] = b0[tid]; bias1[tid] = b1[tid]; Was[tid] = Wa[tid]; }
    for (int i = tid; i < 192; i += THREADS) Wc2s[i] = Wc2[i];
    if (tid >= 192 && tid < 256) bc1s[tid - 192] = bc1[tid - 192];
    // static pad: dir-enc cols 152..159 are never overwritten -> zero once
    if (ht < 64) {
        int rr = ht >> 1, cc = 152 + (ht & 1) * 4;
        #pragma unroll
        for (int c = 0; c < 4; c++) {
            Ah[rr * LDA + cc + c] = bz;
            Al[rr * LDA + cc + c] = bz;
        }
    }
    __syncthreads();

    const int cnt    = g_cnt;
    const int nTiles = (cnt + BM - 1) >> 5;

    for (int tile = blockIdx.x * 2 + half; tile < nTiles; tile += gridDim.x * 2) {
        const int gi   = (tile << 5) + r;
        const bool live = gi < cnt;

        // ===== S1: positional encoding (cols 0..63): 1 sincosf + 9 doublings/channel =====
        {
            bf16* rh = Ah + r * LDA;
            bf16* rl = Al + r * LDA;
            if (q < 3) {
                float s = 0.f, c = 0.f;
                if (live) sincosf(g_world[gi * 3 + q], &s, &c);
                #pragma unroll
                for (int j = 0; j < 10; j++) {
                    bf16 h, l;
                    split_bf16(s, h, l); rh[q * 20 + j] = h;      rl[q * 20 + j] = l;
                    split_bf16(c, h, l); rh[q * 20 + 10 + j] = h; rl[q * 20 + 10 + j] = l;
                    float ns = 2.f * s * c;
                    float nc = fmaf(-2.f * s, s, 1.f);
                    s = ns; c = nc;
                }
            } else {
                #pragma unroll
                for (int c = 60; c < 64; c++) { rh[c] = bz; rl[c] = bz; }
            }
        }
        HBAR(barid);

        // ===== L0: C = enc @ W0 (K=64, N=128) =====
        wmma_layer<4, 4, LDW>(Ah, Al, W0h, W0l, Cs, r16, cb64);
        HBAR(barid);

        // ===== L0 epilogue: h0 = relu(C + b0) -> cols 0..127 (32 cols/thread) =====
        {
            const float* crow = Cs + r * LDC;
            bf16* rh = Ah + r * LDA;
            bf16* rl = Al + r * LDA;
            int c0i = q * 32;
            #pragma unroll
            for (int c = 0; c < 32; c += 4) {
                float4 cv = *reinterpret_cast<const float4*>(crow + c0i + c);
                float4 bv = *reinterpret_cast<const float4*>(bias0 + c0i + c);
                epi4(cv, bv, rh, rl, c0i + c);
            }
        }
        HBAR(barid);

        // ===== L1: C = h0 @ W1 (K=128, N=128) =====
        wmma_layer<8, 4, LDW>(Ah, Al, W1h, W1l, Cs, r16, cb64);
        HBAR(barid);

        // ===== L1 epilogue: h1 = relu(C + b1); alpha; dir encode =====
        {
            const float* crow = Cs + r * LDC;
            bf16* rh = Ah + r * LDA;
            bf16* rl = Al + r * LDA;
            int c0i = q * 32;
            float aacc = 0.f;
            #pragma unroll
            for (int c = 0; c < 32; c += 4) {
                float4 cv = *reinterpret_cast<const float4*>(crow + c0i + c);
                float4 bv = *reinterpret_cast<const float4*>(bias1 + c0i + c);
                float4 wv = *reinterpret_cast<const float4*>(Was + c0i + c);
                float v0 = cv.x + bv.x; v0 = v0 > 0.f ? v0 : 0.f;
                float v1 = cv.y + bv.y; v1 = v1 > 0.f ? v1 : 0.f;
                float v2 = cv.z + bv.z; v2 = v2 > 0.f ? v2 : 0.f;
                float v3 = cv.w + bv.w; v3 = v3 > 0.f ? v3 : 0.f;
                aacc = fmaf(v0, wv.x, aacc); aacc = fmaf(v1, wv.y, aacc);
                aacc = fmaf(v2, wv.z, aacc); aacc = fmaf(v3, wv.w, aacc);
                __nv_bfloat162 h01 = __floats2bfloat162_rn(v0, v1);
                __nv_bfloat162 h23 = __floats2bfloat162_rn(v2, v3);
                __nv_bfloat162 l01 = __floats2bfloat162_rn(v0 - __low2float(h01), v1 - __high2float(h01));
                __nv_bfloat162 l23 = __floats2bfloat162_rn(v2 - __low2float(h23), v3 - __high2float(h23));
                *reinterpret_cast<__nv_bfloat162*>(rh + c0i + c)     = h01;
                *reinterpret_cast<__nv_bfloat162*>(rh + c0i + c + 2) = h23;
                *reinterpret_cast<__nv_bfloat162*>(rl + c0i + c)     = l01;
                *reinterpret_cast<__nv_bfloat162*>(rl + c0i + c + 2) = l23;
            }
            aacc += __shfl_xor_sync(0xffffffffu, aacc, 1);
            aacc += __shfl_xor_sync(0xffffffffu, aacc, 2);
            if (q == 0) alph[r] = 1.0f / (1.0f + __expf(-(aacc + ba0)));

            // dir encode (cols 128..151): 1 sincosf + 3 doublings/channel
            if (q < 3) {
                float s = 0.f, c = 0.f;
                if (live) sincosf(g_vd[gi * 3 + q], &s, &c);
                #pragma unroll
                for (int j = 0; j < 4; j++) {
                    bf16 h, l;
                    split_bf16(s, h, l); rh[128 + q * 8 + j] = h;     rl[128 + q * 8 + j] = l;
                    split_bf16(c, h, l); rh[128 + q * 8 + 4 + j] = h; rl[128 + q * 8 + 4 + j] = l;
                    float ns = 2.f * s * c;
                    float nc = fmaf(-2.f * s, s, 1.f);
                    s = ns; c = nc;
                }
            }
        }
        HBAR(barid);

        // ===== Wc1: C = [h1 | denc] @ Wc1 (K=160, N=64) =====
        wmma_layer<10, 2, LDWC>(Ah, Al, Wc1h, Wc1l, Cs, r16, cb32);
        HBAR(barid);

        // ===== final: hc = relu(C + bc1); rgb = sigmoid(hc @ Wc2 + bc2); scatter =====
        {
            const float* crow = Cs + r * LDC;
            int c0i = q * 16;
            float a0 = 0.f, a1 = 0.f, a2 = 0.f;
            #pragma unroll
            for (int c = 0; c < 16; c++) {
                float h = crow[c0i + c] + bc1s[c0i + c];
                h = h > 0.f ? h : 0.f;
                a0 = fmaf(h, Wc2s[(c0i + c) * 3 + 0], a0);
                a1 = fmaf(h, Wc2s[(c0i + c) * 3 + 1], a1);
                a2 = fmaf(h, Wc2s[(c0i + c) * 3 + 2], a2);
            }
            a0 += __shfl_xor_sync(0xffffffffu, a0, 1);
            a0 += __shfl_xor_sync(0xffffffffu, a0, 2);
            a1 += __shfl_xor_sync(0xffffffffu, a1, 1);
            a1 += __shfl_xor_sync(0xffffffffu, a1, 2);
            a2 += __shfl_xor_sync(0xffffffffu, a2, 1);
            a2 += __shfl_xor_sync(0xffffffffu, a2, 2);
            if (q == 0 && live) {
                float4 outv;
                outv.x = 1.0f / (1.0f + __expf(-(a0 + bc20)));
                outv.y = 1.0f / (1.0f + __expf(-(a1 + bc21)));
                outv.z = 1.0f / (1.0f + __expf(-(a2 + bc22)));
                outv.w = alph[r];
                *reinterpret_cast<float4*>(&g_rgba[g_sidx[gi] * 4]) = outv;
            }
        }
        HBAR(barid);
    }
}

// ---------------- kernel 5: composite (register bitonic sort) ----------------
__global__ void __launch_bounds__(128) k_composite(float* __restrict__ out)
{
    int n = blockIdx.x * blockDim.x + threadIdx.x;
    if (n >= N_RAYS) return;

    float tv[N_PLANES];
    int   pv[N_PLANES];
    #pragma unroll
    for (int p = 0; p < N_PLANES; p++) {
        tv[p] = g_t[p * N_RAYS + n];
        pv[p] = p;
    }

    #pragma unroll
    for (int k = 2; k <= N_PLANES; k <<= 1) {
        #pragma unroll
        for (int j = k >> 1; j > 0; j >>= 1) {
            #pragma unroll
            for (int i = 0; i < N_PLANES; i++) {
                int l = i ^ j;
                if (l > i) {
                    bool up = ((i & k) == 0);
                    bool sw = up ? (tv[i] > tv[l]) : (tv[i] < tv[l]);
                    if (sw) {
                        float tt = tv[i]; tv[i] = tv[l]; tv[l] = tt;
                        int   pp = pv[i]; pv[i] = pv[l]; pv[l] = pp;
                    }
                }
            }
        }
    }

    float trans = 1.0f, sw = 0.0f, depth = 0.0f;
    float c0 = 0.f, c1 = 0.f, c2 = 0.f;
    #pragma unroll
    for (int s = 0; s < N_PLANES; s++) {
        int p = pv[s];
        float4 rg = *reinterpret_cast<const float4*>(&g_rgba[(p * N_RAYS + n) * 4]);
        float a = rg.w;
        float w = a * trans;
        depth = fmaf(tv[s], w, depth);
        c0 = fmaf(rg.x, w, c0);
        c1 = fmaf(rg.y, w, c1);
        c2 = fmaf(rg.z, w, c2);
        sw += w;
        trans *= (1.0f - a);
    }
    float bg = 1.0f - sw;
    out[n * 4 + 0] = c0 + bg;
    out[n * 4 + 1] = c1 + bg;
    out[n * 4 + 2] = c2 + bg;
    out[n * 4 + 3] = depth;
}

// ---------------- launch ----------------
extern "C" void kernel_launch(void* const* d_in, const int* in_sizes, int n_in,
                              void* d_out, int out_size)
{
    const float* ndc    = (const float*)d_in[0];
    const float* campos = (const float*)d_in[1];
    const float* camR   = (const float*)d_in[2];
    const float* basis  = (const float*)d_in[3];
    const float* center = (const float*)d_in[4];
    const float* wh     = (const float*)d_in[5];
    const float* W0     = (const float*)d_in[6];
    const float* b0     = (const float*)d_in[7];
    const float* W1     = (const float*)d_in[8];
    const float* b1     = (const float*)d_in[9];
    const float* Wa     = (const float*)d_in[10];
    const float* ba     = (const float*)d_in[11];
    const float* Wc1    = (const float*)d_in[12];
    const float* bc1    = (const float*)d_in[13];
    const float* Wc2    = (const float*)d_in[14];
    const float* bc2    = (const float*)d_in[15];
    float* out = (float*)d_out;

    static int smem_set = 0;
    if (!smem_set) {
        cudaFuncSetAttribute(k_mlp, cudaFuncAttributeMaxDynamicSharedMemorySize, SMEM_BYTES);
        smem_set = 1;
    }

    k_reset<<<1, 32>>>();
    k_geom<<<NSAMP / 256, 256>>>(ndc, campos, camR, basis, center, wh);
    k_mlp<<<PERSIST_BLOCKS, THREADS, SMEM_BYTES>>>(W0, b0, W1, b1, Wa, ba, Wc1, bc1, Wc2, bc2);
    k_composite<<<(N_RAYS + 127) / 128, 128>>>(out);
}

// round 12
// speedup vs baseline: 2.1160x; 1.6602x over previous
#include <cuda_runtime.h>
#include <cuda_bf16.h>
#include <math.h>
#include <stdint.h>

#define N_RAYS   32768
#define N_PLANES 32
#define NSAMP    (N_RAYS * N_PLANES)
#define EPSV     1e-8f
#define PERSIST_BLOCKS 148
#define THREADS  256

// ---------------- scratch ----------------
__device__ int   g_cnt;
__device__ int   g_sidx[NSAMP];
__device__ float g_world[NSAMP * 3];
__device__ float g_vd[NSAMP * 3];
__device__ float g_t[NSAMP];
__device__ float g_rgba[NSAMP * 4];

// ---------------- kernel 0 ----------------
__global__ void k_reset() { if (threadIdx.x == 0) g_cnt = 0; }

// ---------------- kernel 1: geometry + compaction ----------------
__global__ void __launch_bounds__(256) k_geom(
    const float* __restrict__ ndc, const float* __restrict__ cam_pos,
    const float* __restrict__ cam_R, const float* __restrict__ basis,
    const float* __restrict__ center, const float* __restrict__ wh)
{
    int gid = blockIdx.x * blockDim.x + threadIdx.x;
    if (gid >= NSAMP) return;
    int p = gid / N_RAYS;
    int n = gid - p * N_RAYS;

    float nd0 = ndc[n * 3 + 0], nd1 = ndc[n * 3 + 1], nd2 = ndc[n * 3 + 2];
    float d0 = cam_R[0] * nd0 + cam_R[1] * nd1 + cam_R[2] * nd2;
    float d1 = cam_R[3] * nd0 + cam_R[4] * nd1 + cam_R[5] * nd2;
    float d2 = cam_R[6] * nd0 + cam_R[7] * nd1 + cam_R[8] * nd2;
    float o0 = cam_pos[0], o1 = cam_pos[1], o2 = cam_pos[2];

    const float* B = basis + p * 9;
    float pn0 = B[2], pn1 = B[5], pn2 = B[8];
    float c0 = center[p * 3 + 0], c1 = center[p * 3 + 1], c2 = center[p * 3 + 2];

    float denom = pn0 * d0 + pn1 * d1 + pn2 * d2;
    if (fabsf(denom) < EPSV) denom = EPSV;
    float num = (c0 - o0) * pn0 + (c1 - o1) * pn1 + (c2 - o2) * pn2;
    float t = num / denom;

    float w0 = o0 + t * d0, w1 = o1 + t * d1, w2 = o2 + t * d2;
    float u = (w0 - c0) * B[0] + (w1 - c1) * B[3] + (w2 - c2) * B[6];
    float v = (w0 - c0) * B[1] + (w1 - c1) * B[4] + (w2 - c2) * B[7];
    bool inside = (fabsf(u) <= wh[p * 2 + 0] * 0.5f) && (fabsf(v) <= wh[p * 2 + 1] * 0.5f);
    bool hit = inside && (t > 0.0f);

    g_t[gid] = t;

    unsigned mask = __ballot_sync(0xffffffffu, hit);
    if (hit) {
        int lane   = threadIdx.x & 31;
        int leader = __ffs(mask) - 1;
        int rank   = __popc(mask & ((1u << lane) - 1u));
        int base   = 0;
        if (lane == leader) base = atomicAdd(&g_cnt, __popc(mask));
        base = __shfl_sync(mask, base, leader);
        int i = base + rank;
        g_sidx[i] = gid;
        g_world[i * 3 + 0] = w0;
        g_world[i * 3 + 1] = w1;
        g_world[i * 3 + 2] = w2;
        float vd0 = w0 - o0, vd1 = w1 - o1, vd2 = w2 - o2;
        float inv = 1.0f / (sqrtf(vd0 * vd0 + vd1 * vd1 + vd2 * vd2) + EPSV);
        g_vd[i * 3 + 0] = vd0 * inv;
        g_vd[i * 3 + 1] = vd1 * inv;
        g_vd[i * 3 + 2] = vd2 * inv;
    } else {
        float4 z = make_float4(0.f, 0.f, 0.f, 0.f);
        *reinterpret_cast<float4*>(&g_rgba[gid * 4]) = z;
    }
}

// ================= PTX mma/ldmatrix helpers =================
typedef __nv_bfloat16 bf16;

__device__ __forceinline__ uint32_t cvta_smem(const void* p) {
    uint32_t a;
    asm("{ .reg .u64 t; cvta.to.shared.u64 t, %1; cvt.u32.u64 %0, t; }" : "=r"(a) : "l"(p));
    return a;
}
__device__ __forceinline__ void ldm_x4(uint32_t r[4], uint32_t addr) {
    asm volatile("ldmatrix.sync.aligned.m8n8.x4.shared.b16 {%0,%1,%2,%3}, [%4];"
        : "=r"(r[0]), "=r"(r[1]), "=r"(r[2]), "=r"(r[3]) : "r"(addr));
}
__device__ __forceinline__ void ldm_x4t(uint32_t r[4], uint32_t addr) {
    asm volatile("ldmatrix.sync.aligned.m8n8.x4.trans.shared.b16 {%0,%1,%2,%3}, [%4];"
        : "=r"(r[0]), "=r"(r[1]), "=r"(r[2]), "=r"(r[3]) : "r"(addr));
}
__device__ __forceinline__ void mma_bf16(float c[4], const uint32_t a[4], uint32_t b0, uint32_t b1) {
    asm volatile("mma.sync.aligned.m16n8k16.row.col.f32.bf16.bf16.f32 "
        "{%0,%1,%2,%3}, {%4,%5,%6,%7}, {%8,%9}, {%0,%1,%2,%3};"
        : "+f"(c[0]), "+f"(c[1]), "+f"(c[2]), "+f"(c[3])
        : "r"(a[0]), "r"(a[1]), "r"(a[2]), "r"(a[3]), "r"(b0), "r"(b1));
}
// per-lane byte offset for an ldmatrix tile with row stride ldB bytes
__device__ __forceinline__ uint32_t lane_mat_off(uint32_t lane, uint32_t ldB) {
    uint32_t i = lane & 7, m = lane >> 3;
    return (i + (m & 1) * 8) * ldB + (m >> 1) * 16;
}

// K-loop core with 2-term bf16 split (3 mma per n8-frag)
template <int KSTEPS, int NPAIRS>
__device__ __forceinline__ void mma_core(
    uint32_t aHi, uint32_t aLo, uint32_t bHi, uint32_t bLo, uint32_t ldbB,
    float acc[][4])
{
    #pragma unroll
    for (int ks = 0; ks < KSTEPS; ks++) {
        uint32_t ah[4], al[4];
        ldm_x4(ah, aHi + ks * 32);
        ldm_x4(al, aLo + ks * 32);
        uint32_t bkHi = bHi + ks * 16 * ldbB;
        uint32_t bkLo = bLo + ks * 16 * ldbB;
        #pragma unroll
        for (int p = 0; p < NPAIRS; p++) {
            uint32_t bh[4], bl[4];
            ldm_x4t(bh, bkHi + p * 32);
            ldm_x4t(bl, bkLo + p * 32);
            mma_bf16(acc[2 * p],     ah, bh[0], bh[1]);
            mma_bf16(acc[2 * p],     ah, bl[0], bl[1]);
            mma_bf16(acc[2 * p],     al, bh[0], bh[1]);
            mma_bf16(acc[2 * p + 1], ah, bh[2], bh[3]);
            mma_bf16(acc[2 * p + 1], ah, bl[2], bl[3]);
            mma_bf16(acc[2 * p + 1], al, bh[2], bh[3]);
        }
    }
}

// ---------------- smem layout (bytes) ----------------
#define LDW_B   272     // W0/W1 row stride (136 bf16)
#define LDWC_B  144     // Wc1 row stride (72 bf16)
#define LDA0_B  336     // A0 row stride (168 bf16)
#define LDA1_B  272     // A1 row stride (136 bf16)

#define SM_W0H   0
#define SM_W0L   (SM_W0H + 64 * LDW_B)      // 17408
#define SM_W1H   (SM_W0L + 64 * LDW_B)      // 34816
#define SM_W1L   (SM_W1H + 128 * LDW_B)     // 69632
#define SM_WC1H  (SM_W1L + 128 * LDW_B)     // 104448
#define SM_WC1L  (SM_WC1H + 160 * LDWC_B)   // 127488
#define SM_A0    (SM_WC1L + 160 * LDWC_B)   // 150528 : per half, hi+lo blocks
#define A0_BLK   (32 * LDA0_B)
#define SM_A1    (SM_A0 + 4 * A0_BLK)       // 193536
#define A1_BLK   (32 * LDA1_B)
#define SM_PART  (SM_A1 + 4 * A1_BLK)       // 228352 : 2 x [32][2][4] floats
#define SM_WC2T  (SM_PART + 2048)           // 230400 : [3][64] floats
#define SM_BC1   (SM_WC2T + 768)            // 231168 : 64 floats
#define SM_WAS   (SM_BC1 + 256)             // 231424 : 128 floats
#define SMEM_BYTES (SM_WAS + 512)           // 231936

#define HBAR(id) asm volatile("bar.sync %0, %1;" :: "r"(id), "r"(128) : "memory")

__device__ __forceinline__ void split_bf16(float w, bf16& h, bf16& l) {
    h = __float2bfloat16(w);
    l = __float2bfloat16(w - __bfloat162float(h));
}

__device__ void stage_weight(const float* __restrict__ W, char* smem,
                             int hoff, int loff, int N, int Ksrc, int Kpad, int ldB, int tid)
{
    for (int idx = tid; idx < Kpad * N; idx += THREADS) {
        int k = idx / N;
        int n = idx - k * N;
        float w = (k < Ksrc) ? W[k * N + n] : 0.0f;
        bf16 h, l; split_bf16(w, h, l);
        *reinterpret_cast<bf16*>(smem + hoff + k * ldB + n * 2) = h;
        *reinterpret_cast<bf16*>(smem + loff + k * ldB + n * 2) = l;
    }
}

__global__ void __launch_bounds__(THREADS, 1) k_mlp(
    const float* __restrict__ W0,  const float* __restrict__ b0,
    const float* __restrict__ W1,  const float* __restrict__ b1,
    const float* __restrict__ Wa,  const float* __restrict__ ba,
    const float* __restrict__ Wc1, const float* __restrict__ bc1,
    const float* __restrict__ Wc2, const float* __restrict__ bc2)
{
    extern __shared__ char smem[];
    const uint32_t smem_u = cvta_smem(smem);

    const int tid  = threadIdx.x;
    const int half = tid >> 7;
    const int ht   = tid & 127;
    const int lane = tid & 31;
    const int hw   = ht >> 5;             // warp within half, 0..3
    const int r16  = (hw >> 1) * 16;      // row stripe
    const int cw   = hw & 1;              // col warp
    const int cb64 = cw * 64;             // col base, N=128 layers
    const int cb32 = cw * 32;             // col base, N=64 layer
    const int r    = ht >> 2;             // sample row 0..31
    const int q    = ht & 3;
    const int barid = half + 1;

    // per-half buffer offsets
    const int a0h = SM_A0 + half * 2 * A0_BLK;
    const int a0l = a0h + A0_BLK;
    const int a1h = SM_A1 + half * 2 * A1_BLK;
    const int a1l = a1h + A1_BLK;
    float* part = reinterpret_cast<float*>(smem + SM_PART + half * 1024);  // [32][2][4]
    float* Wc2t = reinterpret_cast<float*>(smem + SM_WC2T);
    float* bc1s = reinterpret_cast<float*>(smem + SM_BC1);
    float* Was  = reinterpret_cast<float*>(smem + SM_WAS);

    const float ba0  = ba[0];
    const float bc20 = bc2[0], bc21 = bc2[1], bc22 = bc2[2];
    const bf16 bz = __float2bfloat16(0.f);

    // lane offsets for ldmatrix tiles
    const uint32_t lo336 = lane_mat_off(lane, LDA0_B);
    const uint32_t lo272 = lane_mat_off(lane, LDW_B);
    const uint32_t lo144 = lane_mat_off(lane, LDWC_B);

    // MMA base addresses (per warp)
    const uint32_t A0Hu = smem_u + a0h + r16 * LDA0_B + lo336;
    const uint32_t A0Lu = smem_u + a0l + r16 * LDA0_B + lo336;
    const uint32_t A1Hu = smem_u + a1h + r16 * LDA1_B + lo272;
    const uint32_t A1Lu = smem_u + a1l + r16 * LDA1_B + lo272;
    const uint32_t W0Hu = smem_u + SM_W0H + cb64 * 2 + lo272;
    const uint32_t W0Lu = smem_u + SM_W0L + cb64 * 2 + lo272;
    const uint32_t W1Hu = smem_u + SM_W1H + cb64 * 2 + lo272;
    const uint32_t W1Lu = smem_u + SM_W1L + cb64 * 2 + lo272;
    const uint32_t WcHu = smem_u + SM_WC1H + cb32 * 2 + lo144;
    const uint32_t WcLu = smem_u + SM_WC1L + cb32 * 2 + lo144;

    // epilogue indices (fragment layout)
    const int ecol = (lane & 3) * 2;      // column pair base within frag
    const int erlo = r16 + (lane >> 2);   // row for c0/c1
    const int erhi = erlo + 8;            // row for c2/c3

    // ---- one-time staging ----
    stage_weight(W0,  smem, SM_W0H,  SM_W0L,  128, 60,  64,  LDW_B,  tid);
    stage_weight(W1,  smem, SM_W1H,  SM_W1L,  128, 128, 128, LDW_B,  tid);
    stage_weight(Wc1, smem, SM_WC1H, SM_WC1L, 64,  152, 160, LDWC_B, tid);
    if (tid < 192) Wc2t[(tid % 3) * 64 + tid / 3] = Wc2[tid];
    if (tid >= 192 && tid < 256) bc1s[tid - 192] = bc1[tid - 192];
    if (tid < 128) Was[tid] = Wa[tid];
    // zero static pad cols 152..159 of A0 (both halves, hi+lo)
    for (int idx = tid; idx < 2 * 32 * 8; idx += THREADS) {
        int hh = idx >> 8, rr = (idx >> 3) & 31, cc = 152 + (idx & 7);
        *reinterpret_cast<bf16*>(smem + SM_A0 + hh * 2 * A0_BLK + rr * LDA0_B + cc * 2) = bz;
        *reinterpret_cast<bf16*>(smem + SM_A0 + hh * 2 * A0_BLK + A0_BLK + rr * LDA0_B + cc * 2) = bz;
    }
    __syncthreads();

    const int cnt    = g_cnt;
    const int nTiles = (cnt + 31) >> 5;

    for (int tile = blockIdx.x * 2 + half; tile < nTiles; tile += gridDim.x * 2) {
        const int gi   = (tile << 5) + r;
        const bool live = gi < cnt;

        // ===== S1: pos encode (cols 0..59) + zero pad 60..63 + dir encode (128..151) =====
        {
            char* rh = smem + a0h + r * LDA0_B;
            char* rl = smem + a0l + r * LDA0_B;
            if (q < 3) {
                float s = 0.f, c = 0.f;
                if (live) sincosf(g_world[gi * 3 + q], &s, &c);
                #pragma unroll
                for (int j = 0; j < 10; j++) {
                    bf16 h, l;
                    split_bf16(s, h, l);
                    *reinterpret_cast<bf16*>(rh + (q * 20 + j) * 2) = h;
                    *reinterpret_cast<bf16*>(rl + (q * 20 + j) * 2) = l;
                    split_bf16(c, h, l);
                    *reinterpret_cast<bf16*>(rh + (q * 20 + 10 + j) * 2) = h;
                    *reinterpret_cast<bf16*>(rl + (q * 20 + 10 + j) * 2) = l;
                    float ns = 2.f * s * c;
                    float nc = fmaf(-2.f * s, s, 1.f);
                    s = ns; c = nc;
                }
                float s2 = 0.f, c2 = 0.f;
                if (live) sincosf(g_vd[gi * 3 + q], &s2, &c2);
                #pragma unroll
                for (int j = 0; j < 4; j++) {
                    bf16 h, l;
                    split_bf16(s2, h, l);
                    *reinterpret_cast<bf16*>(rh + (128 + q * 8 + j) * 2) = h;
                    *reinterpret_cast<bf16*>(rl + (128 + q * 8 + j) * 2) = l;
                    split_bf16(c2, h, l);
                    *reinterpret_cast<bf16*>(rh + (128 + q * 8 + 4 + j) * 2) = h;
                    *reinterpret_cast<bf16*>(rl + (128 + q * 8 + 4 + j) * 2) = l;
                    float ns = 2.f * s2 * c2;
                    float nc = fmaf(-2.f * s2, s2, 1.f);
                    s2 = ns; c2 = nc;
                }
            } else {
                #pragma unroll
                for (int cc = 60; cc < 64; cc++) {
                    *reinterpret_cast<bf16*>(rh + cc * 2) = bz;
                    *reinterpret_cast<bf16*>(rl + cc * 2) = bz;
                }
            }
        }
        HBAR(barid);

        // ===== L0: h0 = relu(enc @ W0 + b0) -> A1 (in-register epilogue) =====
        {
            float acc[8][4];
            #pragma unroll
            for (int i = 0; i < 8; i++)
                #pragma unroll
                for (int j = 0; j < 4; j++) acc[i][j] = 0.f;
            mma_core<4, 4>(A0Hu, A0Lu, W0Hu, W0Lu, LDW_B, acc);
            char* dHlo = smem + a1h + erlo * LDA1_B;
            char* dHhi = smem + a1h + erhi * LDA1_B;
            char* dLlo = smem + a1l + erlo * LDA1_B;
            char* dLhi = smem + a1l + erhi * LDA1_B;
            #pragma unroll
            for (int nf = 0; nf < 8; nf++) {
                int col = cb64 + nf * 8 + ecol;
                float2 bv = __ldg(reinterpret_cast<const float2*>(b0 + col));
                float v0 = fmaxf(acc[nf][0] + bv.x, 0.f);
                float v1 = fmaxf(acc[nf][1] + bv.y, 0.f);
                float v2 = fmaxf(acc[nf][2] + bv.x, 0.f);
                float v3 = fmaxf(acc[nf][3] + bv.y, 0.f);
                __nv_bfloat162 h01 = __floats2bfloat162_rn(v0, v1);
                __nv_bfloat162 h23 = __floats2bfloat162_rn(v2, v3);
                __nv_bfloat162 l01 = __floats2bfloat162_rn(v0 - __low2float(h01), v1 - __high2float(h01));
                __nv_bfloat162 l23 = __floats2bfloat162_rn(v2 - __low2float(h23), v3 - __high2float(h23));
                *reinterpret_cast<uint32_t*>(dHlo + col * 2) = *reinterpret_cast<uint32_t*>(&h01);
                *reinterpret_cast<uint32_t*>(dHhi + col * 2) = *reinterpret_cast<uint32_t*>(&h23);
                *reinterpret_cast<uint32_t*>(dLlo + col * 2) = *reinterpret_cast<uint32_t*>(&l01);
                *reinterpret_cast<uint32_t*>(dLhi + col * 2) = *reinterpret_cast<uint32_t*>(&l23);
            }
        }
        HBAR(barid);

        // ===== L1: h1 = relu(h0 @ W1 + b1) -> A0 cols 0..127; alpha partials =====
        {
            float acc[8][4];
            #pragma unroll
            for (int i = 0; i < 8; i++)
                #pragma unroll
                for (int j = 0; j < 4; j++) acc[i][j] = 0.f;
            mma_core<8, 4>(A1Hu, A1Lu, W1Hu, W1Lu, LDW_B, acc);
            char* dHlo = smem + a0h + erlo * LDA0_B;
            char* dHhi = smem + a0h + erhi * LDA0_B;
            char* dLlo = smem + a0l + erlo * LDA0_B;
            char* dLhi = smem + a0l + erhi * LDA0_B;
            float alo = 0.f, ahi = 0.f;
            #pragma unroll
            for (int nf = 0; nf < 8; nf++) {
                int col = cb64 + nf * 8 + ecol;
                float2 bv = __ldg(reinterpret_cast<const float2*>(b1 + col));
                float2 wv = *reinterpret_cast<const float2*>(Was + col);
                float v0 = fmaxf(acc[nf][0] + bv.x, 0.f);
                float v1 = fmaxf(acc[nf][1] + bv.y, 0.f);
                float v2 = fmaxf(acc[nf][2] + bv.x, 0.f);
                float v3 = fmaxf(acc[nf][3] + bv.y, 0.f);
                alo = fmaf(v0, wv.x, alo); alo = fmaf(v1, wv.y, alo);
                ahi = fmaf(v2, wv.x, ahi); ahi = fmaf(v3, wv.y, ahi);
                __nv_bfloat162 h01 = __floats2bfloat162_rn(v0, v1);
                __nv_bfloat162 h23 = __floats2bfloat162_rn(v2, v3);
                __nv_bfloat162 l01 = __floats2bfloat162_rn(v0 - __low2float(h01), v1 - __high2float(h01));
                __nv_bfloat162 l23 = __floats2bfloat162_rn(v2 - __low2float(h23), v3 - __high2float(h23));
                *reinterpret_cast<uint32_t*>(dHlo + col * 2) = *reinterpret_cast<uint32_t*>(&h01);
                *reinterpret_cast<uint32_t*>(dHhi + col * 2) = *reinterpret_cast<uint32_t*>(&h23);
                *reinterpret_cast<uint32_t*>(dLlo + col * 2) = *reinterpret_cast<uint32_t*>(&l01);
                *reinterpret_cast<uint32_t*>(dLhi + col * 2) = *reinterpret_cast<uint32_t*>(&l23);
            }
            alo += __shfl_xor_sync(0xffffffffu, alo, 1);
            alo += __shfl_xor_sync(0xffffffffu, alo, 2);
            ahi += __shfl_xor_sync(0xffffffffu, ahi, 1);
            ahi += __shfl_xor_sync(0xffffffffu, ahi, 2);
            if ((lane & 3) == 0) {
                part[erlo * 8 + cw * 4 + 3] = alo;
                part[erhi * 8 + cw * 4 + 3] = ahi;
            }
        }
        HBAR(barid);

        // ===== Wc1: hc = relu([h1|denc] @ Wc1 + bc1); rgb partials in-register =====
        {
            float acc[4][4];
            #pragma unroll
            for (int i = 0; i < 4; i++)
                #pragma unroll
                for (int j = 0; j < 4; j++) acc[i][j] = 0.f;
            mma_core<10, 2>(A0Hu, A0Lu, WcHu, WcLu, LDWC_B, acc);
            float plo[3] = {0.f, 0.f, 0.f}, phi[3] = {0.f, 0.f, 0.f};
            #pragma unroll
            for (int nf = 0; nf < 4; nf++) {
                int col = cb32 + nf * 8 + ecol;
                float2 bcv = *reinterpret_cast<const float2*>(bc1s + col);
                float v0 = fmaxf(acc[nf][0] + bcv.x, 0.f);
                float v1 = fmaxf(acc[nf][1] + bcv.y, 0.f);
                float v2 = fmaxf(acc[nf][2] + bcv.x, 0.f);
                float v3 = fmaxf(acc[nf][3] + bcv.y, 0.f);
                #pragma unroll
                for (int j = 0; j < 3; j++) {
                    float2 w = *reinterpret_cast<const float2*>(Wc2t + j * 64 + col);
                    plo[j] = fmaf(v0, w.x, plo[j]); plo[j] = fmaf(v1, w.y, plo[j]);
                    phi[j] = fmaf(v2, w.x, phi[j]); phi[j] = fmaf(v3, w.y, phi[j]);
                }
            }
            #pragma unroll
            for (int j = 0; j < 3; j++) {
                plo[j] += __shfl_xor_sync(0xffffffffu, plo[j], 1);
                plo[j] += __shfl_xor_sync(0xffffffffu, plo[j], 2);
                phi[j] += __shfl_xor_sync(0xffffffffu, phi[j], 1);
                phi[j] += __shfl_xor_sync(0xffffffffu, phi[j], 2);
            }
            if ((lane & 3) == 0) {
                #pragma unroll
                for (int j = 0; j < 3; j++) {
                    part[erlo * 8 + cw * 4 + j] = plo[j];
                    part[erhi * 8 + cw * 4 + j] = phi[j];
                }
            }
        }
        HBAR(barid);

        // ===== combine + scatter (32 threads per half) =====
        if (ht < 32) {
            int gi2 = (tile << 5) + ht;
            if (gi2 < cnt) {
                const float* pp = part + ht * 8;
                float4 outv;
                outv.x = 1.0f / (1.0f + __expf(-(pp[0] + pp[4] + bc20)));
                outv.y = 1.0f / (1.0f + __expf(-(pp[1] + pp[5] + bc21)));
                outv.z = 1.0f / (1.0f + __expf(-(pp[2] + pp[6] + bc22)));
                outv.w = 1.0f / (1.0f + __expf(-(pp[3] + pp[7] + ba0)));
                *reinterpret_cast<float4*>(&g_rgba[g_sidx[gi2] * 4]) = outv;
            }
        }
        HBAR(barid);
    }
}

// ---------------- kernel 5: composite (register bitonic sort) ----------------
__global__ void __launch_bounds__(128) k_composite(float* __restrict__ out)
{
    int n = blockIdx.x * blockDim.x + threadIdx.x;
    if (n >= N_RAYS) return;

    float tv[N_PLANES];
    int   pv[N_PLANES];
    #pragma unroll
    for (int p = 0; p < N_PLANES; p++) {
        tv[p] = g_t[p * N_RAYS + n];
        pv[p] = p;
    }

    #pragma unroll
    for (int k = 2; k <= N_PLANES; k <<= 1) {
        #pragma unroll
        for (int j = k >> 1; j > 0; j >>= 1) {
            #pragma unroll
            for (int i = 0; i < N_PLANES; i++) {
                int l = i ^ j;
                if (l > i) {
                    bool up = ((i & k) == 0);
                    bool sw = up ? (tv[i] > tv[l]) : (tv[i] < tv[l]);
                    if (sw) {
                        float tt = tv[i]; tv[i] = tv[l]; tv[l] = tt;
                        int   pp = pv[i]; pv[i] = pv[l]; pv[l] = pp;
                    }
                }
            }
        }
    }

    float trans = 1.0f, sw = 0.0f, depth = 0.0f;
    float c0 = 0.f, c1 = 0.f, c2 = 0.f;
    #pragma unroll
    for (int s = 0; s < N_PLANES; s++) {
        int p = pv[s];
        float4 rg = *reinterpret_cast<const float4*>(&g_rgba[(p * N_RAYS + n) * 4]);
        float a = rg.w;
        float w = a * trans;
        depth = fmaf(tv[s], w, depth);
        c0 = fmaf(rg.x, w, c0);
        c1 = fmaf(rg.y, w, c1);
        c2 = fmaf(rg.z, w, c2);
        sw += w;
        trans *= (1.0f - a);
    }
    float bg = 1.0f - sw;
    out[n * 4 + 0] = c0 + bg;
    out[n * 4 + 1] = c1 + bg;
    out[n * 4 + 2] = c2 + bg;
    out[n * 4 + 3] = depth;
}

// ---------------- launch ----------------
extern "C" void kernel_launch(void* const* d_in, const int* in_sizes, int n_in,
                              void* d_out, int out_size)
{
    const float* ndc    = (const float*)d_in[0];
    const float* campos = (const float*)d_in[1];
    const float* camR   = (const float*)d_in[2];
    const float* basis  = (const float*)d_in[3];
    const float* center = (const float*)d_in[4];
    const float* wh     = (const float*)d_in[5];
    const float* W0     = (const float*)d_in[6];
    const float* b0     = (const float*)d_in[7];
    const float* W1     = (const float*)d_in[8];
    const float* b1     = (const float*)d_in[9];
    const float* Wa     = (const float*)d_in[10];
    const float* ba     = (const float*)d_in[11];
    const float* Wc1    = (const float*)d_in[12];
    const float* bc1    = (const float*)d_in[13];
    const float* Wc2    = (const float*)d_in[14];
    const float* bc2    = (const float*)d_in[15];
    float* out = (float*)d_out;

    static int smem_set = 0;
    if (!smem_set) {
        cudaFuncSetAttribute(k_mlp, cudaFuncAttributeMaxDynamicSharedMemorySize, SMEM_BYTES);
        smem_set = 1;
    }

    k_reset<<<1, 32>>>();
    k_geom<<<NSAMP / 256, 256>>>(ndc, campos, camR, basis, center, wh);
    k_mlp<<<PERSIST_BLOCKS, THREADS, SMEM_BYTES>>>(W0, b0, W1, b1, Wa, ba, Wc1, bc1, Wc2, bc2);
    k_composite<<<(N_RAYS + 127) / 128, 128>>>(out);
}

// round 13
// speedup vs baseline: 2.5055x; 1.1841x over previous
#include <cuda_runtime.h>
#include <cuda_fp16.h>
#include <math.h>
#include <stdint.h>

#define N_RAYS   32768
#define N_PLANES 32
#define NSAMP    (N_RAYS * N_PLANES)
#define EPSV     1e-8f
#define PERSIST_BLOCKS 148
#define THREADS  256

// ---------------- scratch ----------------
__device__ int   g_cnt;
__device__ int   g_sidx[NSAMP];
__device__ float g_world[NSAMP * 3];
__device__ float g_vd[NSAMP * 3];
__device__ float g_t[NSAMP];
__device__ float g_rgba[NSAMP * 4];

// ---------------- kernel 0 ----------------
__global__ void k_reset() { if (threadIdx.x == 0) g_cnt = 0; }

// ---------------- kernel 1: geometry + compaction ----------------
__global__ void __launch_bounds__(256) k_geom(
    const float* __restrict__ ndc, const float* __restrict__ cam_pos,
    const float* __restrict__ cam_R, const float* __restrict__ basis,
    const float* __restrict__ center, const float* __restrict__ wh)
{
    int gid = blockIdx.x * blockDim.x + threadIdx.x;
    if (gid >= NSAMP) return;
    int p = gid / N_RAYS;
    int n = gid - p * N_RAYS;

    float nd0 = ndc[n * 3 + 0], nd1 = ndc[n * 3 + 1], nd2 = ndc[n * 3 + 2];
    float d0 = cam_R[0] * nd0 + cam_R[1] * nd1 + cam_R[2] * nd2;
    float d1 = cam_R[3] * nd0 + cam_R[4] * nd1 + cam_R[5] * nd2;
    float d2 = cam_R[6] * nd0 + cam_R[7] * nd1 + cam_R[8] * nd2;
    float o0 = cam_pos[0], o1 = cam_pos[1], o2 = cam_pos[2];

    const float* B = basis + p * 9;
    float pn0 = B[2], pn1 = B[5], pn2 = B[8];
    float c0 = center[p * 3 + 0], c1 = center[p * 3 + 1], c2 = center[p * 3 + 2];

    float denom = pn0 * d0 + pn1 * d1 + pn2 * d2;
    if (fabsf(denom) < EPSV) denom = EPSV;
    float num = (c0 - o0) * pn0 + (c1 - o1) * pn1 + (c2 - o2) * pn2;
    float t = num / denom;

    float w0 = o0 + t * d0, w1 = o1 + t * d1, w2 = o2 + t * d2;
    float u = (w0 - c0) * B[0] + (w1 - c1) * B[3] + (w2 - c2) * B[6];
    float v = (w0 - c0) * B[1] + (w1 - c1) * B[4] + (w2 - c2) * B[7];
    bool inside = (fabsf(u) <= wh[p * 2 + 0] * 0.5f) && (fabsf(v) <= wh[p * 2 + 1] * 0.5f);
    bool hit = inside && (t > 0.0f);

    g_t[gid] = t;

    unsigned mask = __ballot_sync(0xffffffffu, hit);
    if (hit) {
        int lane   = threadIdx.x & 31;
        int leader = __ffs(mask) - 1;
        int rank   = __popc(mask & ((1u << lane) - 1u));
        int base   = 0;
        if (lane == leader) base = atomicAdd(&g_cnt, __popc(mask));
        base = __shfl_sync(mask, base, leader);
        int i = base + rank;
        g_sidx[i] = gid;
        g_world[i * 3 + 0] = w0;
        g_world[i * 3 + 1] = w1;
        g_world[i * 3 + 2] = w2;
        float vd0 = w0 - o0, vd1 = w1 - o1, vd2 = w2 - o2;
        float inv = 1.0f / (sqrtf(vd0 * vd0 + vd1 * vd1 + vd2 * vd2) + EPSV);
        g_vd[i * 3 + 0] = vd0 * inv;
        g_vd[i * 3 + 1] = vd1 * inv;
        g_vd[i * 3 + 2] = vd2 * inv;
    } else {
        float4 z = make_float4(0.f, 0.f, 0.f, 0.f);
        *reinterpret_cast<float4*>(&g_rgba[gid * 4]) = z;
    }
}

// ================= PTX mma/ldmatrix helpers =================
__device__ __forceinline__ uint32_t cvta_smem(const void* p) {
    uint32_t a;
    asm("{ .reg .u64 t; cvta.to.shared.u64 t, %1; cvt.u32.u64 %0, t; }" : "=r"(a) : "l"(p));
    return a;
}
__device__ __forceinline__ void ldm_x4(uint32_t r[4], uint32_t addr) {
    asm volatile("ldmatrix.sync.aligned.m8n8.x4.shared.b16 {%0,%1,%2,%3}, [%4];"
        : "=r"(r[0]), "=r"(r[1]), "=r"(r[2]), "=r"(r[3]) : "r"(addr));
}
__device__ __forceinline__ void ldm_x4t(uint32_t r[4], uint32_t addr) {
    asm volatile("ldmatrix.sync.aligned.m8n8.x4.trans.shared.b16 {%0,%1,%2,%3}, [%4];"
        : "=r"(r[0]), "=r"(r[1]), "=r"(r[2]), "=r"(r[3]) : "r"(addr));
}
__device__ __forceinline__ void mma_f16(float c[4], const uint32_t a[4], uint32_t b0, uint32_t b1) {
    asm volatile("mma.sync.aligned.m16n8k16.row.col.f32.f16.f16.f32 "
        "{%0,%1,%2,%3}, {%4,%5,%6,%7}, {%8,%9}, {%0,%1,%2,%3};"
        : "+f"(c[0]), "+f"(c[1]), "+f"(c[2]), "+f"(c[3])
        : "r"(a[0]), "r"(a[1]), "r"(a[2]), "r"(a[3]), "r"(b0), "r"(b1));
}
// per-lane byte offset for an ldmatrix tile with row stride ldB bytes
__device__ __forceinline__ uint32_t lane_mat_off(uint32_t lane, uint32_t ldB) {
    uint32_t i = lane & 7, m = lane >> 3;
    return (i + (m & 1) * 8) * ldB + (m >> 1) * 16;
}

// K-loop core: A single fp16, B split hi/lo (2 mma per n8-frag)
template <int KSTEPS, int NPAIRS>
__device__ __forceinline__ void mma_core(
    uint32_t aBase, uint32_t bHi, uint32_t bLo, uint32_t ldbB,
    float acc[][4])
{
    #pragma unroll
    for (int ks = 0; ks < KSTEPS; ks++) {
        uint32_t a[4];
        ldm_x4(a, aBase + ks * 32);
        uint32_t bkHi = bHi + ks * 16 * ldbB;
        uint32_t bkLo = bLo + ks * 16 * ldbB;
        #pragma unroll
        for (int p = 0; p < NPAIRS; p++) {
            uint32_t bh[4], bl[4];
            ldm_x4t(bh, bkHi + p * 32);
            ldm_x4t(bl, bkLo + p * 32);
            mma_f16(acc[2 * p],     a, bh[0], bh[1]);
            mma_f16(acc[2 * p],     a, bl[0], bl[1]);
            mma_f16(acc[2 * p + 1], a, bh[2], bh[3]);
            mma_f16(acc[2 * p + 1], a, bl[2], bl[3]);
        }
    }
}

// ---------------- smem layout (bytes) ----------------
#define LDW_B   272     // W0/W1 row stride (136 fp16)
#define LDWC_B  144     // Wc1 row stride (72 fp16)
#define LDA0_B  336     // A0 row stride (168 fp16)
#define LDA1_B  272     // A1 row stride (136 fp16)

#define SM_W0H   0
#define SM_W0L   (SM_W0H + 64 * LDW_B)      // 17408
#define SM_W1H   (SM_W0L + 64 * LDW_B)      // 34816
#define SM_W1L   (SM_W1H + 128 * LDW_B)     // 69632
#define SM_WC1H  (SM_W1L + 128 * LDW_B)     // 104448
#define SM_WC1L  (SM_WC1H + 160 * LDWC_B)   // 127488
#define SM_A0    (SM_WC1L + 160 * LDWC_B)   // 150528 : one block per half
#define A0_BLK   (32 * LDA0_B)              // 10752
#define SM_A1    (SM_A0 + 2 * A0_BLK)       // 172032
#define A1_BLK   (32 * LDA1_B)              // 8704
#define SM_PART  (SM_A1 + 2 * A1_BLK)       // 189440 : 2 x [32][2][4] floats
#define SM_WC2T  (SM_PART + 2048)           // 191488 : [3][64] floats
#define SM_BC1   (SM_WC2T + 768)            // 192256 : 64 floats
#define SM_WAS   (SM_BC1 + 256)             // 192512 : 128 floats
#define SMEM_BYTES (SM_WAS + 512)           // 193024

#define HBAR(id) asm volatile("bar.sync %0, %1;" :: "r"(id), "r"(128) : "memory")

__device__ __forceinline__ void split_f16(float w, __half& h, __half& l) {
    h = __float2half_rn(w);
    l = __float2half_rn(w - __half2float(h));
}

// stage weights: 2-term fp16 split
__device__ void stage_weight(const float* __restrict__ W, char* smem,
                             int hoff, int loff, int N, int Ksrc, int Kpad, int ldB, int tid)
{
    for (int idx = tid; idx < Kpad * N; idx += THREADS) {
        int k = idx / N;
        int n = idx - k * N;
        float w = (k < Ksrc) ? W[k * N + n] : 0.0f;
        __half h, l; split_f16(w, h, l);
        *reinterpret_cast<__half*>(smem + hoff + k * ldB + n * 2) = h;
        *reinterpret_cast<__half*>(smem + loff + k * ldB + n * 2) = l;
    }
}

__global__ void __launch_bounds__(THREADS, 1) k_mlp(
    const float* __restrict__ W0,  const float* __restrict__ b0,
    const float* __restrict__ W1,  const float* __restrict__ b1,
    const float* __restrict__ Wa,  const float* __restrict__ ba,
    const float* __restrict__ Wc1, const float* __restrict__ bc1,
    const float* __restrict__ Wc2, const float* __restrict__ bc2)
{
    extern __shared__ char smem[];
    const uint32_t smem_u = cvta_smem(smem);

    const int tid  = threadIdx.x;
    const int half = tid >> 7;
    const int ht   = tid & 127;
    const int lane = tid & 31;
    const int hw   = ht >> 5;             // warp within half, 0..3
    const int r16  = (hw >> 1) * 16;      // row stripe
    const int cw   = hw & 1;              // col warp
    const int cb64 = cw * 64;             // col base, N=128 layers
    const int cb32 = cw * 32;             // col base, N=64 layer
    const int r    = ht >> 2;             // sample row 0..31
    const int q    = ht & 3;
    const int barid = half + 1;

    // per-half buffer offsets
    const int a0b = SM_A0 + half * A0_BLK;
    const int a1b = SM_A1 + half * A1_BLK;
    float* part = reinterpret_cast<float*>(smem + SM_PART + half * 1024);  // [32][2][4]
    float* Wc2t = reinterpret_cast<float*>(smem + SM_WC2T);
    float* bc1s = reinterpret_cast<float*>(smem + SM_BC1);
    float* Was  = reinterpret_cast<float*>(smem + SM_WAS);

    const float ba0  = ba[0];
    const float bc20 = bc2[0], bc21 = bc2[1], bc22 = bc2[2];
    const __half hz = __float2half_rn(0.f);

    // lane offsets for ldmatrix tiles
    const uint32_t lo336 = lane_mat_off(lane, LDA0_B);
    const uint32_t lo272 = lane_mat_off(lane, LDW_B);
    const uint32_t lo144 = lane_mat_off(lane, LDWC_B);

    // MMA base addresses (per warp)
    const uint32_t A0u  = smem_u + a0b + r16 * LDA0_B + lo336;
    const uint32_t A1u  = smem_u + a1b + r16 * LDA1_B + lo272;
    const uint32_t W0Hu = smem_u + SM_W0H + cb64 * 2 + lo272;
    const uint32_t W0Lu = smem_u + SM_W0L + cb64 * 2 + lo272;
    const uint32_t W1Hu = smem_u + SM_W1H + cb64 * 2 + lo272;
    const uint32_t W1Lu = smem_u + SM_W1L + cb64 * 2 + lo272;
    const uint32_t WcHu = smem_u + SM_WC1H + cb32 * 2 + lo144;
    const uint32_t WcLu = smem_u + SM_WC1L + cb32 * 2 + lo144;

    // epilogue indices (fragment layout)
    const int ecol = (lane & 3) * 2;      // column pair base within frag
    const int erlo = r16 + (lane >> 2);   // row for c0/c1
    const int erhi = erlo + 8;            // row for c2/c3

    // ---- one-time staging ----
    stage_weight(W0,  smem, SM_W0H,  SM_W0L,  128, 60,  64,  LDW_B,  tid);
    stage_weight(W1,  smem, SM_W1H,  SM_W1L,  128, 128, 128, LDW_B,  tid);
    stage_weight(Wc1, smem, SM_WC1H, SM_WC1L, 64,  152, 160, LDWC_B, tid);
    if (tid < 192) Wc2t[(tid % 3) * 64 + tid / 3] = Wc2[tid];
    if (tid >= 192 && tid < 256) bc1s[tid - 192] = bc1[tid - 192];
    if (tid < 128) Was[tid] = Wa[tid];
    // zero static pad cols 152..159 of A0 (both halves)
    for (int idx = tid; idx < 2 * 32 * 8; idx += THREADS) {
        int hh = idx >> 8, rr = (idx >> 3) & 31, cc = 152 + (idx & 7);
        *reinterpret_cast<__half*>(smem + SM_A0 + hh * A0_BLK + rr * LDA0_B + cc * 2) = hz;
    }
    __syncthreads();

    const int cnt    = g_cnt;
    const int nTiles = (cnt + 31) >> 5;

    for (int tile = blockIdx.x * 2 + half; tile < nTiles; tile += gridDim.x * 2) {
        const int gi   = (tile << 5) + r;
        const bool live = gi < cnt;

        // ===== S1: pos encode (cols 0..59) + pad 60..63 + dir encode (128..151) =====
        {
            char* rw = smem + a0b + r * LDA0_B;
            if (q < 3) {
                float s = 0.f, c = 0.f;
                if (live) sincosf(g_world[gi * 3 + q], &s, &c);
                #pragma unroll
                for (int j = 0; j < 10; j++) {
                    *reinterpret_cast<__half*>(rw + (q * 20 + j) * 2)      = __float2half_rn(s);
                    *reinterpret_cast<__half*>(rw + (q * 20 + 10 + j) * 2) = __float2half_rn(c);
                    float ns = 2.f * s * c;
                    float nc = fmaf(-2.f * s, s, 1.f);
                    s = ns; c = nc;
                }
                float s2 = 0.f, c2 = 0.f;
                if (live) sincosf(g_vd[gi * 3 + q], &s2, &c2);
                #pragma unroll
                for (int j = 0; j < 4; j++) {
                    *reinterpret_cast<__half*>(rw + (128 + q * 8 + j) * 2)     = __float2half_rn(s2);
                    *reinterpret_cast<__half*>(rw + (128 + q * 8 + 4 + j) * 2) = __float2half_rn(c2);
                    float ns = 2.f * s2 * c2;
                    float nc = fmaf(-2.f * s2, s2, 1.f);
                    s2 = ns; c2 = nc;
                }
            } else {
                #pragma unroll
                for (int cc = 60; cc < 64; cc++)
                    *reinterpret_cast<__half*>(rw + cc * 2) = hz;
            }
        }
        HBAR(barid);

        // ===== L0: h0 = relu(enc @ W0 + b0) -> A1 (in-register epilogue) =====
        {
            float acc[8][4];
            #pragma unroll
            for (int i = 0; i < 8; i++)
                #pragma unroll
                for (int j = 0; j < 4; j++) acc[i][j] = 0.f;
            mma_core<4, 4>(A0u, W0Hu, W0Lu, LDW_B, acc);
            char* dlo = smem + a1b + erlo * LDA1_B;
            char* dhi = smem + a1b + erhi * LDA1_B;
            #pragma unroll
            for (int nf = 0; nf < 8; nf++) {
                int col = cb64 + nf * 8 + ecol;
                float2 bv = __ldg(reinterpret_cast<const float2*>(b0 + col));
                float v0 = fmaxf(acc[nf][0] + bv.x, 0.f);
                float v1 = fmaxf(acc[nf][1] + bv.y, 0.f);
                float v2 = fmaxf(acc[nf][2] + bv.x, 0.f);
                float v3 = fmaxf(acc[nf][3] + bv.y, 0.f);
                __half2 h01 = __floats2half2_rn(v0, v1);
                __half2 h23 = __floats2half2_rn(v2, v3);
                *reinterpret_cast<uint32_t*>(dlo + col * 2) = *reinterpret_cast<uint32_t*>(&h01);
                *reinterpret_cast<uint32_t*>(dhi + col * 2) = *reinterpret_cast<uint32_t*>(&h23);
            }
        }
        HBAR(barid);

        // ===== L1: h1 = relu(h0 @ W1 + b1) -> A0 cols 0..127; alpha partials =====
        {
            float acc[8][4];
            #pragma unroll
            for (int i = 0; i < 8; i++)
                #pragma unroll
                for (int j = 0; j < 4; j++) acc[i][j] = 0.f;
            mma_core<8, 4>(A1u, W1Hu, W1Lu, LDW_B, acc);
            char* dlo = smem + a0b + erlo * LDA0_B;
            char* dhi = smem + a0b + erhi * LDA0_B;
            float alo = 0.f, ahi = 0.f;
            #pragma unroll
            for (int nf = 0; nf < 8; nf++) {
                int col = cb64 + nf * 8 + ecol;
                float2 bv = __ldg(reinterpret_cast<const float2*>(b1 + col));
                float2 wv = *reinterpret_cast<const float2*>(Was + col);
                float v0 = fmaxf(acc[nf][0] + bv.x, 0.f);
                float v1 = fmaxf(acc[nf][1] + bv.y, 0.f);
                float v2 = fmaxf(acc[nf][2] + bv.x, 0.f);
                float v3 = fmaxf(acc[nf][3] + bv.y, 0.f);
                alo = fmaf(v0, wv.x, alo); alo = fmaf(v1, wv.y, alo);
                ahi = fmaf(v2, wv.x, ahi); ahi = fmaf(v3, wv.y, ahi);
                __half2 h01 = __floats2half2_rn(v0, v1);
                __half2 h23 = __floats2half2_rn(v2, v3);
                *reinterpret_cast<uint32_t*>(dlo + col * 2) = *reinterpret_cast<uint32_t*>(&h01);
                *reinterpret_cast<uint32_t*>(dhi + col * 2) = *reinterpret_cast<uint32_t*>(&h23);
            }
            alo += __shfl_xor_sync(0xffffffffu, alo, 1);
            alo += __shfl_xor_sync(0xffffffffu, alo, 2);
            ahi += __shfl_xor_sync(0xffffffffu, ahi, 1);
            ahi += __shfl_xor_sync(0xffffffffu, ahi, 2);
            if ((lane & 3) == 0) {
                part[erlo * 8 + cw * 4 + 3] = alo;
                part[erhi * 8 + cw * 4 + 3] = ahi;
            }
        }
        HBAR(barid);

        // ===== Wc1: hc = relu([h1|denc] @ Wc1 + bc1); rgb partials in-register =====
        {
            float acc[4][4];
            #pragma unroll
            for (int i = 0; i < 4; i++)
                #pragma unroll
                for (int j = 0; j < 4; j++) acc[i][j] = 0.f;
            mma_core<10, 2>(A0u, WcHu, WcLu, LDWC_B, acc);
            float plo[3] = {0.f, 0.f, 0.f}, phi[3] = {0.f, 0.f, 0.f};
            #pragma unroll
            for (int nf = 0; nf < 4; nf++) {
                int col = cb32 + nf * 8 + ecol;
                float2 bcv = *reinterpret_cast<const float2*>(bc1s + col);
                float v0 = fmaxf(acc[nf][0] + bcv.x, 0.f);
                float v1 = fmaxf(acc[nf][1] + bcv.y, 0.f);
                float v2 = fmaxf(acc[nf][2] + bcv.x, 0.f);
                float v3 = fmaxf(acc[nf][3] + bcv.y, 0.f);
                #pragma unroll
                for (int j = 0; j < 3; j++) {
                    float2 w = *reinterpret_cast<const float2*>(Wc2t + j * 64 + col);
                    plo[j] = fmaf(v0, w.x, plo[j]); plo[j] = fmaf(v1, w.y, plo[j]);
                    phi[j] = fmaf(v2, w.x, phi[j]); phi[j] = fmaf(v3, w.y, phi[j]);
                }
            }
            #pragma unroll
            for (int j = 0; j < 3; j++) {
                plo[j] += __shfl_xor_sync(0xffffffffu, plo[j], 1);
                plo[j] += __shfl_xor_sync(0xffffffffu, plo[j], 2);
                phi[j] += __shfl_xor_sync(0xffffffffu, phi[j], 1);
                phi[j] += __shfl_xor_sync(0xffffffffu, phi[j], 2);
            }
            if ((lane & 3) == 0) {
                #pragma unroll
                for (int j = 0; j < 3; j++) {
                    part[erlo * 8 + cw * 4 + j] = plo[j];
                    part[erhi * 8 + cw * 4 + j] = phi[j];
                }
            }
        }
        HBAR(barid);

        // ===== combine + scatter (32 threads per half) =====
        if (ht < 32) {
            int gi2 = (tile << 5) + ht;
            if (gi2 < cnt) {
                const float* pp = part + ht * 8;
                float4 outv;
                outv.x = 1.0f / (1.0f + __expf(-(pp[0] + pp[4] + bc20)));
                outv.y = 1.0f / (1.0f + __expf(-(pp[1] + pp[5] + bc21)));
                outv.z = 1.0f / (1.0f + __expf(-(pp[2] + pp[6] + bc22)));
                outv.w = 1.0f / (1.0f + __expf(-(pp[3] + pp[7] + ba0)));
                *reinterpret_cast<float4*>(&g_rgba[g_sidx[gi2] * 4]) = outv;
            }
        }
        HBAR(barid);
    }
}

// ---------------- kernel 5: composite (register bitonic sort) ----------------
__global__ void __launch_bounds__(128) k_composite(float* __restrict__ out)
{
    int n = blockIdx.x * blockDim.x + threadIdx.x;
    if (n >= N_RAYS) return;

    float tv[N_PLANES];
    int   pv[N_PLANES];
    #pragma unroll
    for (int p = 0; p < N_PLANES; p++) {
        tv[p] = g_t[p * N_RAYS + n];
        pv[p] = p;
    }

    #pragma unroll
    for (int k = 2; k <= N_PLANES; k <<= 1) {
        #pragma unroll
        for (int j = k >> 1; j > 0; j >>= 1) {
            #pragma unroll
            for (int i = 0; i < N_PLANES; i++) {
                int l = i ^ j;
                if (l > i) {
                    bool up = ((i & k) == 0);
                    bool sw = up ? (tv[i] > tv[l]) : (tv[i] < tv[l]);
                    if (sw) {
                        float tt = tv[i]; tv[i] = tv[l]; tv[l] = tt;
                        int   pp = pv[i]; pv[i] = pv[l]; pv[l] = pp;
                    }
                }
            }
        }
    }

    float trans = 1.0f, sw = 0.0f, depth = 0.0f;
    float c0 = 0.f, c1 = 0.f, c2 = 0.f;
    #pragma unroll
    for (int s = 0; s < N_PLANES; s++) {
        int p = pv[s];
        float4 rg = *reinterpret_cast<const float4*>(&g_rgba[(p * N_RAYS + n) * 4]);
        float a = rg.w;
        float w = a * trans;
        depth = fmaf(tv[s], w, depth);
        c0 = fmaf(rg.x, w, c0);
        c1 = fmaf(rg.y, w, c1);
        c2 = fmaf(rg.z, w, c2);
        sw += w;
        trans *= (1.0f - a);
    }
    float bg = 1.0f - sw;
    out[n * 4 + 0] = c0 + bg;
    out[n * 4 + 1] = c1 + bg;
    out[n * 4 + 2] = c2 + bg;
    out[n * 4 + 3] = depth;
}

// ---------------- launch ----------------
extern "C" void kernel_launch(void* const* d_in, const int* in_sizes, int n_in,
                              void* d_out, int out_size)
{
    const float* ndc    = (const float*)d_in[0];
    const float* campos = (const float*)d_in[1];
    const float* camR   = (const float*)d_in[2];
    const float* basis  = (const float*)d_in[3];
    const float* center = (const float*)d_in[4];
    const float* wh     = (const float*)d_in[5];
    const float* W0     = (const float*)d_in[6];
    const float* b0     = (const float*)d_in[7];
    const float* W1     = (const float*)d_in[8];
    const float* b1     = (const float*)d_in[9];
    const float* Wa     = (const float*)d_in[10];
    const float* ba     = (const float*)d_in[11];
    const float* Wc1    = (const float*)d_in[12];
    const float* bc1    = (const float*)d_in[13];
    const float* Wc2    = (const float*)d_in[14];
    const float* bc2    = (const float*)d_in[15];
    float* out = (float*)d_out;

    static int smem_set = 0;
    if (!smem_set) {
        cudaFuncSetAttribute(k_mlp, cudaFuncAttributeMaxDynamicSharedMemorySize, SMEM_BYTES);
        smem_set = 1;
    }

    k_reset<<<1, 32>>>();
    k_geom<<<NSAMP / 256, 256>>>(ndc, campos, camR, basis, center, wh);
    k_mlp<<<PERSIST_BLOCKS, THREADS, SMEM_BYTES>>>(W0, b0, W1, b1, Wa, ba, Wc1, bc1, Wc2, bc2);
    k_composite<<<(N_RAYS + 127) / 128, 128>>>(out);
}

// round 14
// speedup vs baseline: 3.0172x; 1.2042x over previous
#include <cuda_runtime.h>
#include <cuda_fp16.h>
#include <math.h>
#include <stdint.h>

#define N_RAYS   32768
#define N_PLANES 32
#define NSAMP    (N_RAYS * N_PLANES)
#define EPSV     1e-8f
#define PERSIST_BLOCKS 148
#define THREADS  256

// ---------------- scratch ----------------
__device__ int   g_cnt;
__device__ int   g_sidx[NSAMP];
__device__ float g_world[NSAMP * 3];
__device__ float g_vd[NSAMP * 3];
__device__ float g_t[NSAMP];
__device__ float g_rgba[NSAMP * 4];

// ---------------- kernel 0 ----------------
__global__ void k_reset() { if (threadIdx.x == 0) g_cnt = 0; }

// ---------------- kernel 1: geometry + compaction ----------------
__global__ void __launch_bounds__(256) k_geom(
    const float* __restrict__ ndc, const float* __restrict__ cam_pos,
    const float* __restrict__ cam_R, const float* __restrict__ basis,
    const float* __restrict__ center, const float* __restrict__ wh)
{
    int gid = blockIdx.x * blockDim.x + threadIdx.x;
    if (gid >= NSAMP) return;
    int p = gid / N_RAYS;
    int n = gid - p * N_RAYS;

    float nd0 = ndc[n * 3 + 0], nd1 = ndc[n * 3 + 1], nd2 = ndc[n * 3 + 2];
    float d0 = cam_R[0] * nd0 + cam_R[1] * nd1 + cam_R[2] * nd2;
    float d1 = cam_R[3] * nd0 + cam_R[4] * nd1 + cam_R[5] * nd2;
    float d2 = cam_R[6] * nd0 + cam_R[7] * nd1 + cam_R[8] * nd2;
    float o0 = cam_pos[0], o1 = cam_pos[1], o2 = cam_pos[2];

    const float* B = basis + p * 9;
    float pn0 = B[2], pn1 = B[5], pn2 = B[8];
    float c0 = center[p * 3 + 0], c1 = center[p * 3 + 1], c2 = center[p * 3 + 2];

    float denom = pn0 * d0 + pn1 * d1 + pn2 * d2;
    if (fabsf(denom) < EPSV) denom = EPSV;
    float num = (c0 - o0) * pn0 + (c1 - o1) * pn1 + (c2 - o2) * pn2;
    float t = num / denom;

    float w0 = o0 + t * d0, w1 = o1 + t * d1, w2 = o2 + t * d2;
    float u = (w0 - c0) * B[0] + (w1 - c1) * B[3] + (w2 - c2) * B[6];
    float v = (w0 - c0) * B[1] + (w1 - c1) * B[4] + (w2 - c2) * B[7];
    bool inside = (fabsf(u) <= wh[p * 2 + 0] * 0.5f) && (fabsf(v) <= wh[p * 2 + 1] * 0.5f);
    bool hit = inside && (t > 0.0f);

    g_t[gid] = t;

    unsigned mask = __ballot_sync(0xffffffffu, hit);
    if (hit) {
        int lane   = threadIdx.x & 31;
        int leader = __ffs(mask) - 1;
        int rank   = __popc(mask & ((1u << lane) - 1u));
        int base   = 0;
        if (lane == leader) base = atomicAdd(&g_cnt, __popc(mask));
        base = __shfl_sync(mask, base, leader);
        int i = base + rank;
        g_sidx[i] = gid;
        g_world[i * 3 + 0] = w0;
        g_world[i * 3 + 1] = w1;
        g_world[i * 3 + 2] = w2;
        float vd0 = w0 - o0, vd1 = w1 - o1, vd2 = w2 - o2;
        float inv = 1.0f / (sqrtf(vd0 * vd0 + vd1 * vd1 + vd2 * vd2) + EPSV);
        g_vd[i * 3 + 0] = vd0 * inv;
        g_vd[i * 3 + 1] = vd1 * inv;
        g_vd[i * 3 + 2] = vd2 * inv;
    } else {
        float4 z = make_float4(0.f, 0.f, 0.f, 0.f);
        *reinterpret_cast<float4*>(&g_rgba[gid * 4]) = z;
    }
}

// ================= PTX mma/ldmatrix helpers =================
__device__ __forceinline__ uint32_t cvta_smem(const void* p) {
    uint32_t a;
    asm("{ .reg .u64 t; cvta.to.shared.u64 t, %1; cvt.u32.u64 %0, t; }" : "=r"(a) : "l"(p));
    return a;
}
__device__ __forceinline__ void ldm_x4(uint32_t r[4], uint32_t addr) {
    asm volatile("ldmatrix.sync.aligned.m8n8.x4.shared.b16 {%0,%1,%2,%3}, [%4];"
        : "=r"(r[0]), "=r"(r[1]), "=r"(r[2]), "=r"(r[3]) : "r"(addr));
}
__device__ __forceinline__ void ldm_x4t(uint32_t r[4], uint32_t addr) {
    asm volatile("ldmatrix.sync.aligned.m8n8.x4.trans.shared.b16 {%0,%1,%2,%3}, [%4];"
        : "=r"(r[0]), "=r"(r[1]), "=r"(r[2]), "=r"(r[3]) : "r"(addr));
}
__device__ __forceinline__ void mma_f16(float c[4], const uint32_t a[4], uint32_t b0, uint32_t b1) {
    asm volatile("mma.sync.aligned.m16n8k16.row.col.f32.f16.f16.f32 "
        "{%0,%1,%2,%3}, {%4,%5,%6,%7}, {%8,%9}, {%0,%1,%2,%3};"
        : "+f"(c[0]), "+f"(c[1]), "+f"(c[2]), "+f"(c[3])
        : "r"(a[0]), "r"(a[1]), "r"(a[2]), "r"(a[3]), "r"(b0), "r"(b1));
}
// per-lane byte offset for an ldmatrix tile with row stride ldB bytes
__device__ __forceinline__ uint32_t lane_mat_off(uint32_t lane, uint32_t ldB) {
    uint32_t i = lane & 7, m = lane >> 3;
    return (i + (m & 1) * 8) * ldB + (m >> 1) * 16;
}

// K-loop core: A single fp16, B single fp16 (2 mma per pair = 2 n8-frags)
template <int KSTEPS, int NPAIRS>
__device__ __forceinline__ void mma_core(
    uint32_t aBase, uint32_t bBase, uint32_t ldbB,
    float acc[][4])
{
    #pragma unroll
    for (int ks = 0; ks < KSTEPS; ks++) {
        uint32_t a[4];
        ldm_x4(a, aBase + ks * 32);
        uint32_t bk = bBase + ks * 16 * ldbB;
        #pragma unroll
        for (int p = 0; p < NPAIRS; p++) {
            uint32_t b[4];
            ldm_x4t(b, bk + p * 32);
            mma_f16(acc[2 * p],     a, b[0], b[1]);
            mma_f16(acc[2 * p + 1], a, b[2], b[3]);
        }
    }
}

// ---------------- smem layout (bytes) ----------------
#define LDW_B   272     // W0/W1 row stride (136 fp16)
#define LDWC_B  144     // Wc1 row stride (72 fp16)
#define LDA0_B  336     // A0 row stride (168 fp16)
#define LDA1_B  272     // A1 row stride (136 fp16)

#define SM_W0    0                          // 64*272  = 17408
#define SM_W1    (SM_W0 + 64 * LDW_B)       // 17408 + 128*272 = 52224
#define SM_WC1   (SM_W1 + 128 * LDW_B)      // 52224 + 160*144 = 75264
#define SM_A0    (SM_WC1 + 160 * LDWC_B)    // 75264
#define A0_BLK   (32 * LDA0_B)              // 10752
#define SM_A1    (SM_A0 + 2 * A0_BLK)       // 96768
#define A1_BLK   (32 * LDA1_B)              // 8704
#define SM_PART  (SM_A1 + 2 * A1_BLK)       // 114176 : 2 x [32][2][4] floats
#define SM_WC2T  (SM_PART + 2048)           // 116224 : [3][64] floats
#define SM_BC1   (SM_WC2T + 768)            // 116992 : 64 floats
#define SM_WAS   (SM_BC1 + 256)             // 117248 : 128 floats
#define SMEM_BYTES (SM_WAS + 512)           // 117760

#define HBAR(id) asm volatile("bar.sync %0, %1;" :: "r"(id), "r"(128) : "memory")

// stage weights: single fp16
__device__ void stage_weight(const float* __restrict__ W, char* smem,
                             int off, int N, int Ksrc, int Kpad, int ldB, int tid)
{
    for (int idx = tid; idx < Kpad * N; idx += THREADS) {
        int k = idx / N;
        int n = idx - k * N;
        float w = (k < Ksrc) ? W[k * N + n] : 0.0f;
        *reinterpret_cast<__half*>(smem + off + k * ldB + n * 2) = __float2half_rn(w);
    }
}

__global__ void __launch_bounds__(THREADS, 1) k_mlp(
    const float* __restrict__ W0,  const float* __restrict__ b0,
    const float* __restrict__ W1,  const float* __restrict__ b1,
    const float* __restrict__ Wa,  const float* __restrict__ ba,
    const float* __restrict__ Wc1, const float* __restrict__ bc1,
    const float* __restrict__ Wc2, const float* __restrict__ bc2)
{
    extern __shared__ char smem[];
    const uint32_t smem_u = cvta_smem(smem);

    const int tid  = threadIdx.x;
    const int half = tid >> 7;
    const int ht   = tid & 127;
    const int lane = tid & 31;
    const int hw   = ht >> 5;             // warp within half, 0..3
    const int r16  = (hw >> 1) * 16;      // row stripe
    const int cw   = hw & 1;              // col warp
    const int cb64 = cw * 64;             // col base, N=128 layers
    const int cb32 = cw * 32;             // col base, N=64 layer
    const int r    = ht >> 2;             // sample row 0..31
    const int q    = ht & 3;
    const int barid = half + 1;

    // per-half buffer offsets
    const int a0b = SM_A0 + half * A0_BLK;
    const int a1b = SM_A1 + half * A1_BLK;
    float* part = reinterpret_cast<float*>(smem + SM_PART + half * 1024);  // [32][2][4]
    float* Wc2t = reinterpret_cast<float*>(smem + SM_WC2T);
    float* bc1s = reinterpret_cast<float*>(smem + SM_BC1);
    float* Was  = reinterpret_cast<float*>(smem + SM_WAS);

    const float ba0  = ba[0];
    const float bc20 = bc2[0], bc21 = bc2[1], bc22 = bc2[2];
    const __half hz = __float2half_rn(0.f);

    // lane offsets for ldmatrix tiles
    const uint32_t lo336 = lane_mat_off(lane, LDA0_B);
    const uint32_t lo272 = lane_mat_off(lane, LDW_B);
    const uint32_t lo144 = lane_mat_off(lane, LDWC_B);

    // MMA base addresses (per warp)
    const uint32_t A0u = smem_u + a0b + r16 * LDA0_B + lo336;
    const uint32_t A1u = smem_u + a1b + r16 * LDA1_B + lo272;
    const uint32_t W0u = smem_u + SM_W0 + cb64 * 2 + lo272;
    const uint32_t W1u = smem_u + SM_W1 + cb64 * 2 + lo272;
    const uint32_t Wcu = smem_u + SM_WC1 + cb32 * 2 + lo144;

    // epilogue indices (fragment layout)
    const int ecol = (lane & 3) * 2;      // column pair base within frag
    const int erlo = r16 + (lane >> 2);   // row for c0/c1
    const int erhi = erlo + 8;            // row for c2/c3

    // ---- one-time staging ----
    stage_weight(W0,  smem, SM_W0,  128, 60,  64,  LDW_B,  tid);
    stage_weight(W1,  smem, SM_W1,  128, 128, 128, LDW_B,  tid);
    stage_weight(Wc1, smem, SM_WC1, 64,  152, 160, LDWC_B, tid);
    if (tid < 192) Wc2t[(tid % 3) * 64 + tid / 3] = Wc2[tid];
    if (tid >= 192 && tid < 256) bc1s[tid - 192] = bc1[tid - 192];
    if (tid < 128) Was[tid] = Wa[tid];
    // zero static pad cols 152..159 of A0 (both halves)
    for (int idx = tid; idx < 2 * 32 * 8; idx += THREADS) {
        int hh = idx >> 8, rr = (idx >> 3) & 31, cc = 152 + (idx & 7);
        *reinterpret_cast<__half*>(smem + SM_A0 + hh * A0_BLK + rr * LDA0_B + cc * 2) = hz;
    }
    __syncthreads();

    const int cnt    = g_cnt;
    const int nTiles = (cnt + 31) >> 5;

    for (int tile = blockIdx.x * 2 + half; tile < nTiles; tile += gridDim.x * 2) {
        const int gi   = (tile << 5) + r;
        const bool live = gi < cnt;

        // ===== S1: pos encode (cols 0..59) + pad 60..63 + dir encode (128..151) =====
        {
            char* rw = smem + a0b + r * LDA0_B;
            if (q < 3) {
                float s = 0.f, c = 0.f;
                if (live) sincosf(g_world[gi * 3 + q], &s, &c);
                #pragma unroll
                for (int j = 0; j < 10; j++) {
                    *reinterpret_cast<__half*>(rw + (q * 20 + j) * 2)      = __float2half_rn(s);
                    *reinterpret_cast<__half*>(rw + (q * 20 + 10 + j) * 2) = __float2half_rn(c);
                    float ns = 2.f * s * c;
                    float nc = fmaf(-2.f * s, s, 1.f);
                    s = ns; c = nc;
                }
                float s2 = 0.f, c2 = 0.f;
                if (live) sincosf(g_vd[gi * 3 + q], &s2, &c2);
                #pragma unroll
                for (int j = 0; j < 4; j++) {
                    *reinterpret_cast<__half*>(rw + (128 + q * 8 + j) * 2)     = __float2half_rn(s2);
                    *reinterpret_cast<__half*>(rw + (128 + q * 8 + 4 + j) * 2) = __float2half_rn(c2);
                    float ns = 2.f * s2 * c2;
                    float nc = fmaf(-2.f * s2, s2, 1.f);
                    s2 = ns; c2 = nc;
                }
            } else {
                #pragma unroll
                for (int cc = 60; cc < 64; cc++)
                    *reinterpret_cast<__half*>(rw + cc * 2) = hz;
            }
        }
        HBAR(barid);

        // ===== L0: h0 = relu(enc @ W0 + b0) -> A1 (in-register epilogue) =====
        {
            float acc[8][4];
            #pragma unroll
            for (int i = 0; i < 8; i++)
                #pragma unroll
                for (int j = 0; j < 4; j++) acc[i][j] = 0.f;
            mma_core<4, 4>(A0u, W0u, LDW_B, acc);
            char* dlo = smem + a1b + erlo * LDA1_B;
            char* dhi = smem + a1b + erhi * LDA1_B;
            #pragma unroll
            for (int nf = 0; nf < 8; nf++) {
                int col = cb64 + nf * 8 + ecol;
                float2 bv = __ldg(reinterpret_cast<const float2*>(b0 + col));
                float v0 = fmaxf(acc[nf][0] + bv.x, 0.f);
                float v1 = fmaxf(acc[nf][1] + bv.y, 0.f);
                float v2 = fmaxf(acc[nf][2] + bv.x, 0.f);
                float v3 = fmaxf(acc[nf][3] + bv.y, 0.f);
                __half2 h01 = __floats2half2_rn(v0, v1);
                __half2 h23 = __floats2half2_rn(v2, v3);
                *reinterpret_cast<uint32_t*>(dlo + col * 2) = *reinterpret_cast<uint32_t*>(&h01);
                *reinterpret_cast<uint32_t*>(dhi + col * 2) = *reinterpret_cast<uint32_t*>(&h23);
            }
        }
        HBAR(barid);

        // ===== L1: h1 = relu(h0 @ W1 + b1) -> A0 cols 0..127; alpha partials =====
        {
            float acc[8][4];
            #pragma unroll
            for (int i = 0; i < 8; i++)
                #pragma unroll
                for (int j = 0; j < 4; j++) acc[i][j] = 0.f;
            mma_core<8, 4>(A1u, W1u, LDW_B, acc);
            char* dlo = smem + a0b + erlo * LDA0_B;
            char* dhi = smem + a0b + erhi * LDA0_B;
            float alo = 0.f, ahi = 0.f;
            #pragma unroll
            for (int nf = 0; nf < 8; nf++) {
                int col = cb64 + nf * 8 + ecol;
                float2 bv = __ldg(reinterpret_cast<const float2*>(b1 + col));
                float2 wv = *reinterpret_cast<const float2*>(Was + col);
                float v0 = fmaxf(acc[nf][0] + bv.x, 0.f);
                float v1 = fmaxf(acc[nf][1] + bv.y, 0.f);
                float v2 = fmaxf(acc[nf][2] + bv.x, 0.f);
                float v3 = fmaxf(acc[nf][3] + bv.y, 0.f);
                alo = fmaf(v0, wv.x, alo); alo = fmaf(v1, wv.y, alo);
                ahi = fmaf(v2, wv.x, ahi); ahi = fmaf(v3, wv.y, ahi);
                __half2 h01 = __floats2half2_rn(v0, v1);
                __half2 h23 = __floats2half2_rn(v2, v3);
                *reinterpret_cast<uint32_t*>(dlo + col * 2) = *reinterpret_cast<uint32_t*>(&h01);
                *reinterpret_cast<uint32_t*>(dhi + col * 2) = *reinterpret_cast<uint32_t*>(&h23);
            }
            alo += __shfl_xor_sync(0xffffffffu, alo, 1);
            alo += __shfl_xor_sync(0xffffffffu, alo, 2);
            ahi += __shfl_xor_sync(0xffffffffu, ahi, 1);
            ahi += __shfl_xor_sync(0xffffffffu, ahi, 2);
            if ((lane & 3) == 0) {
                part[erlo * 8 + cw * 4 + 3] = alo;
                part[erhi * 8 + cw * 4 + 3] = ahi;
            }
        }
        HBAR(barid);

        // ===== Wc1: hc = relu([h1|denc] @ Wc1 + bc1); rgb partials in-register =====
        {
            float acc[4][4];
            #pragma unroll
            for (int i = 0; i < 4; i++)
                #pragma unroll
                for (int j = 0; j < 4; j++) acc[i][j] = 0.f;
            mma_core<10, 2>(A0u, Wcu, LDWC_B, acc);
            float plo[3] = {0.f, 0.f, 0.f}, phi[3] = {0.f, 0.f, 0.f};
            #pragma unroll
            for (int nf = 0; nf < 4; nf++) {
                int col = cb32 + nf * 8 + ecol;
                float2 bcv = *reinterpret_cast<const float2*>(bc1s + col);
                float v0 = fmaxf(acc[nf][0] + bcv.x, 0.f);
                float v1 = fmaxf(acc[nf][1] + bcv.y, 0.f);
                float v2 = fmaxf(acc[nf][2] + bcv.x, 0.f);
                float v3 = fmaxf(acc[nf][3] + bcv.y, 0.f);
                #pragma unroll
                for (int j = 0; j < 3; j++) {
                    float2 w = *reinterpret_cast<const float2*>(Wc2t + j * 64 + col);
                    plo[j] = fmaf(v0, w.x, plo[j]); plo[j] = fmaf(v1, w.y, plo[j]);
                    phi[j] = fmaf(v2, w.x, phi[j]); phi[j] = fmaf(v3, w.y, phi[j]);
                }
            }
            #pragma unroll
            for (int j = 0; j < 3; j++) {
                plo[j] += __shfl_xor_sync(0xffffffffu, plo[j], 1);
                plo[j] += __shfl_xor_sync(0xffffffffu, plo[j], 2);
                phi[j] += __shfl_xor_sync(0xffffffffu, phi[j], 1);
                phi[j] += __shfl_xor_sync(0xffffffffu, phi[j], 2);
            }
            if ((lane & 3) == 0) {
                #pragma unroll
                for (int j = 0; j < 3; j++) {
                    part[erlo * 8 + cw * 4 + j] = plo[j];
                    part[erhi * 8 + cw * 4 + j] = phi[j];
                }
            }
        }
        HBAR(barid);

        // ===== combine + scatter (32 threads per half) =====
        if (ht < 32) {
            int gi2 = (tile << 5) + ht;
            if (gi2 < cnt) {
                const float* pp = part + ht * 8;
                float4 outv;
                outv.x = 1.0f / (1.0f + __expf(-(pp[0] + pp[4] + bc20)));
                outv.y = 1.0f / (1.0f + __expf(-(pp[1] + pp[5] + bc21)));
                outv.z = 1.0f / (1.0f + __expf(-(pp[2] + pp[6] + bc22)));
                outv.w = 1.0f / (1.0f + __expf(-(pp[3] + pp[7] + ba0)));
                *reinterpret_cast<float4*>(&g_rgba[g_sidx[gi2] * 4]) = outv;
            }
        }
        HBAR(barid);
    }
}

// ---------------- kernel 5: composite (register bitonic sort) ----------------
__global__ void __launch_bounds__(128) k_composite(float* __restrict__ out)
{
    int n = blockIdx.x * blockDim.x + threadIdx.x;
    if (n >= N_RAYS) return;

    float tv[N_PLANES];
    int   pv[N_PLANES];
    #pragma unroll
    for (int p = 0; p < N_PLANES; p++) {
        tv[p] = g_t[p * N_RAYS + n];
        pv[p] = p;
    }

    #pragma unroll
    for (int k = 2; k <= N_PLANES; k <<= 1) {
        #pragma unroll
        for (int j = k >> 1; j > 0; j >>= 1) {
            #pragma unroll
            for (int i = 0; i < N_PLANES; i++) {
                int l = i ^ j;
                if (l > i) {
                    bool up = ((i & k) == 0);
                    bool sw = up ? (tv[i] > tv[l]) : (tv[i] < tv[l]);
                    if (sw) {
                        float tt = tv[i]; tv[i] = tv[l]; tv[l] = tt;
                        int   pp = pv[i]; pv[i] = pv[l]; pv[l] = pp;
                    }
                }
            }
        }
    }

    float trans = 1.0f, sw = 0.0f, depth = 0.0f;
    float c0 = 0.f, c1 = 0.f, c2 = 0.f;
    #pragma unroll
    for (int s = 0; s < N_PLANES; s++) {
        int p = pv[s];
        float4 rg = *reinterpret_cast<const float4*>(&g_rgba[(p * N_RAYS + n) * 4]);
        float a = rg.w;
        float w = a * trans;
        depth = fmaf(tv[s], w, depth);
        c0 = fmaf(rg.x, w, c0);
        c1 = fmaf(rg.y, w, c1);
        c2 = fmaf(rg.z, w, c2);
        sw += w;
        trans *= (1.0f - a);
    }
    float bg = 1.0f - sw;
    out[n * 4 + 0] = c0 + bg;
    out[n * 4 + 1] = c1 + bg;
    out[n * 4 + 2] = c2 + bg;
    out[n * 4 + 3] = depth;
}

// ---------------- launch ----------------
extern "C" void kernel_launch(void* const* d_in, const int* in_sizes, int n_in,
                              void* d_out, int out_size)
{
    const float* ndc    = (const float*)d_in[0];
    const float* campos = (const float*)d_in[1];
    const float* camR   = (const float*)d_in[2];
    const float* basis  = (const float*)d_in[3];
    const float* center = (const float*)d_in[4];
    const float* wh     = (const float*)d_in[5];
    const float* W0     = (const float*)d_in[6];
    const float* b0     = (const float*)d_in[7];
    const float* W1     = (const float*)d_in[8];
    const float* b1     = (const float*)d_in[9];
    const float* Wa     = (const float*)d_in[10];
    const float* ba     = (const float*)d_in[11];
    const float* Wc1    = (const float*)d_in[12];
    const float* bc1    = (const float*)d_in[13];
    const float* Wc2    = (const float*)d_in[14];
    const float* bc2    = (const float*)d_in[15];
    float* out = (float*)d_out;

    static int smem_set = 0;
    if (!smem_set) {
        cudaFuncSetAttribute(k_mlp, cudaFuncAttributeMaxDynamicSharedMemorySize, SMEM_BYTES);
        smem_set = 1;
    }

    k_reset<<<1, 32>>>();
    k_geom<<<NSAMP / 256, 256>>>(ndc, campos, camR, basis, center, wh);
    k_mlp<<<PERSIST_BLOCKS, THREADS, SMEM_BYTES>>>(W0, b0, W1, b1, Wa, ba, Wc1, bc1, Wc2, bc2);
    k_composite<<<(N_RAYS + 127) / 128, 128>>>(out);
}

// round 15
// speedup vs baseline: 3.6105x; 1.1966x over previous
#include <cuda_runtime.h>
#include <cuda_fp16.h>
#include <math.h>
#include <stdint.h>

#define N_RAYS   32768
#define N_PLANES 32
#define NSAMP    (N_RAYS * N_PLANES)
#define EPSV     1e-8f
#define PERSIST_BLOCKS 148
#define THREADS  256

// ---------------- scratch ----------------
__device__ int   g_cnt;
__device__ int   g_sidx[NSAMP];
__device__ float g_world[NSAMP * 3];
__device__ float g_vd[NSAMP * 3];
__device__ float g_t[NSAMP];
__device__ float g_rgba[NSAMP * 4];

// ---------------- kernel 0 ----------------
__global__ void k_reset() { if (threadIdx.x == 0) g_cnt = 0; }

// ---------------- kernel 1: geometry + compaction ----------------
__global__ void __launch_bounds__(256) k_geom(
    const float* __restrict__ ndc, const float* __restrict__ cam_pos,
    const float* __restrict__ cam_R, const float* __restrict__ basis,
    const float* __restrict__ center, const float* __restrict__ wh)
{
    int gid = blockIdx.x * blockDim.x + threadIdx.x;
    if (gid >= NSAMP) return;
    int p = gid / N_RAYS;
    int n = gid - p * N_RAYS;

    float nd0 = ndc[n * 3 + 0], nd1 = ndc[n * 3 + 1], nd2 = ndc[n * 3 + 2];
    float d0 = cam_R[0] * nd0 + cam_R[1] * nd1 + cam_R[2] * nd2;
    float d1 = cam_R[3] * nd0 + cam_R[4] * nd1 + cam_R[5] * nd2;
    float d2 = cam_R[6] * nd0 + cam_R[7] * nd1 + cam_R[8] * nd2;
    float o0 = cam_pos[0], o1 = cam_pos[1], o2 = cam_pos[2];

    const float* B = basis + p * 9;
    float pn0 = B[2], pn1 = B[5], pn2 = B[8];
    float c0 = center[p * 3 + 0], c1 = center[p * 3 + 1], c2 = center[p * 3 + 2];

    float denom = pn0 * d0 + pn1 * d1 + pn2 * d2;
    if (fabsf(denom) < EPSV) denom = EPSV;
    float num = (c0 - o0) * pn0 + (c1 - o1) * pn1 + (c2 - o2) * pn2;
    float t = num / denom;

    float w0 = o0 + t * d0, w1 = o1 + t * d1, w2 = o2 + t * d2;
    float u = (w0 - c0) * B[0] + (w1 - c1) * B[3] + (w2 - c2) * B[6];
    float v = (w0 - c0) * B[1] + (w1 - c1) * B[4] + (w2 - c2) * B[7];
    bool inside = (fabsf(u) <= wh[p * 2 + 0] * 0.5f) && (fabsf(v) <= wh[p * 2 + 1] * 0.5f);
    bool hit = inside && (t > 0.0f);

    g_t[gid] = t;

    unsigned mask = __ballot_sync(0xffffffffu, hit);
    if (hit) {
        int lane   = threadIdx.x & 31;
        int leader = __ffs(mask) - 1;
        int rank   = __popc(mask & ((1u << lane) - 1u));
        int base   = 0;
        if (lane == leader) base = atomicAdd(&g_cnt, __popc(mask));
        base = __shfl_sync(mask, base, leader);
        int i = base + rank;
        g_sidx[i] = gid;
        g_world[i * 3 + 0] = w0;
        g_world[i * 3 + 1] = w1;
        g_world[i * 3 + 2] = w2;
        float vd0 = w0 - o0, vd1 = w1 - o1, vd2 = w2 - o2;
        float inv = 1.0f / (sqrtf(vd0 * vd0 + vd1 * vd1 + vd2 * vd2) + EPSV);
        g_vd[i * 3 + 0] = vd0 * inv;
        g_vd[i * 3 + 1] = vd1 * inv;
        g_vd[i * 3 + 2] = vd2 * inv;
    } else {
        float4 z = make_float4(0.f, 0.f, 0.f, 0.f);
        *reinterpret_cast<float4*>(&g_rgba[gid * 4]) = z;
    }
}

// ================= PTX mma/ldmatrix helpers =================
__device__ __forceinline__ uint32_t cvta_smem(const void* p) {
    uint32_t a;
    asm("{ .reg .u64 t; cvta.to.shared.u64 t, %1; cvt.u32.u64 %0, t; }" : "=r"(a) : "l"(p));
    return a;
}
__device__ __forceinline__ void ldm_x4(uint32_t r[4], uint32_t addr) {
    asm volatile("ldmatrix.sync.aligned.m8n8.x4.shared.b16 {%0,%1,%2,%3}, [%4];"
        : "=r"(r[0]), "=r"(r[1]), "=r"(r[2]), "=r"(r[3]) : "r"(addr));
}
__device__ __forceinline__ void ldm_x4t(uint32_t r[4], uint32_t addr) {
    asm volatile("ldmatrix.sync.aligned.m8n8.x4.trans.shared.b16 {%0,%1,%2,%3}, [%4];"
        : "=r"(r[0]), "=r"(r[1]), "=r"(r[2]), "=r"(r[3]) : "r"(addr));
}
__device__ __forceinline__ void mma_f16(float c[4], const uint32_t a[4], uint32_t b0, uint32_t b1) {
    asm volatile("mma.sync.aligned.m16n8k16.row.col.f32.f16.f16.f32 "
        "{%0,%1,%2,%3}, {%4,%5,%6,%7}, {%8,%9}, {%0,%1,%2,%3};"
        : "+f"(c[0]), "+f"(c[1]), "+f"(c[2]), "+f"(c[3])
        : "r"(a[0]), "r"(a[1]), "r"(a[2]), "r"(a[3]), "r"(b0), "r"(b1));
}
__device__ __forceinline__ uint32_t lane_mat_off(uint32_t lane, uint32_t ldB) {
    uint32_t i = lane & 7, m = lane >> 3;
    return (i + (m & 1) * 8) * ldB + (m >> 1) * 16;
}

// 64-row warp GEMM: warp covers 64 rows (4 m-frags) x (NB*16) cols.
// B fragments reused across all 4 m-frags.
template <int KSTEPS, int NB>
__device__ __forceinline__ void mma64(
    uint32_t aBase, uint32_t ldaB, uint32_t bBase, uint32_t ldbB,
    float acc[4][2 * NB][4])
{
    #pragma unroll
    for (int ks = 0; ks < KSTEPS; ks++) {
        uint32_t a[4][4];
        #pragma unroll
        for (int mf = 0; mf < 4; mf++)
            ldm_x4(a[mf], aBase + mf * 16 * ldaB + ks * 32);
        uint32_t bk = bBase + ks * 16 * ldbB;
        #pragma unroll
        for (int p = 0; p < NB; p++) {
            uint32_t b[4];
            ldm_x4t(b, bk + p * 32);
            #pragma unroll
            for (int mf = 0; mf < 4; mf++) {
                mma_f16(acc[mf][2 * p],     a[mf], b[0], b[1]);
                mma_f16(acc[mf][2 * p + 1], a[mf], b[2], b[3]);
            }
        }
    }
}

// ---------------- smem layout (bytes) ----------------
#define LDW_B   272     // W0/W1 row stride (136 fp16)
#define LDWC_B  144     // Wc1 row stride (72 fp16)
#define LDA0_B  336     // A0 row stride (168 fp16)
#define LDA1_B  272     // A1 row stride (136 fp16)

#define SM_W0    0                          // 64*272  = 17408
#define SM_W1    (SM_W0 + 64 * LDW_B)       // 17408
#define SM_WC1   (SM_W1 + 128 * LDW_B)      // 52224
#define SM_A0    (SM_WC1 + 160 * LDWC_B)    // 75264
#define A0_BLK   (64 * LDA0_B)              // 21504
#define SM_A1    (SM_A0 + 2 * A0_BLK)       // 118272
#define A1_BLK   (64 * LDA1_B)              // 17408
#define SM_PART  (SM_A1 + 2 * A1_BLK)       // 153088 : 2 x [64][4][4] floats (4096 B each)
#define SM_WC2T  (SM_PART + 8192)           // 161280 : [3][64] floats
#define SM_BC1   (SM_WC2T + 768)            // 162048 : 64 floats
#define SM_WAS   (SM_BC1 + 256)             // 162304 : 128 floats
#define SMEM_BYTES (SM_WAS + 512)           // 162816

#define HBAR(id) asm volatile("bar.sync %0, %1;" :: "r"(id), "r"(128) : "memory")

__device__ void stage_weight(const float* __restrict__ W, char* smem,
                             int off, int N, int Ksrc, int Kpad, int ldB, int tid)
{
    for (int idx = tid; idx < Kpad * N; idx += THREADS) {
        int k = idx / N;
        int n = idx - k * N;
        float w = (k < Ksrc) ? W[k * N + n] : 0.0f;
        *reinterpret_cast<__half*>(smem + off + k * ldB + n * 2) = __float2half_rn(w);
    }
}

__global__ void __launch_bounds__(THREADS, 1) k_mlp(
    const float* __restrict__ W0,  const float* __restrict__ b0,
    const float* __restrict__ W1,  const float* __restrict__ b1,
    const float* __restrict__ Wa,  const float* __restrict__ ba,
    const float* __restrict__ Wc1, const float* __restrict__ bc1,
    const float* __restrict__ Wc2, const float* __restrict__ bc2)
{
    extern __shared__ char smem[];
    const uint32_t smem_u = cvta_smem(smem);

    const int tid  = threadIdx.x;
    const int half = tid >> 7;
    const int ht   = tid & 127;
    const int lane = tid & 31;
    const int hw   = ht >> 5;             // warp within half, 0..3
    const int cb32 = hw * 32;             // col base, N=128 layers
    const int cb16 = hw * 16;             // col base, N=64 layer
    const int r    = ht >> 1;             // sample row 0..63 (2 threads/sample)
    const int q    = ht & 1;
    const int barid = half + 1;

    const int a0b = SM_A0 + half * A0_BLK;
    const int a1b = SM_A1 + half * A1_BLK;
    float* part = reinterpret_cast<float*>(smem + SM_PART + half * 4096);  // [64][4][4]
    float* Wc2t = reinterpret_cast<float*>(smem + SM_WC2T);
    float* bc1s = reinterpret_cast<float*>(smem + SM_BC1);
    float* Was  = reinterpret_cast<float*>(smem + SM_WAS);

    const float ba0  = ba[0];
    const float bc20 = bc2[0], bc21 = bc2[1], bc22 = bc2[2];
    const __half hz = __float2half_rn(0.f);

    const uint32_t lo336 = lane_mat_off(lane, LDA0_B);
    const uint32_t lo272 = lane_mat_off(lane, LDW_B);
    const uint32_t lo144 = lane_mat_off(lane, LDWC_B);

    const uint32_t A0u = smem_u + a0b + lo336;
    const uint32_t A1u = smem_u + a1b + lo272;
    const uint32_t W0u = smem_u + SM_W0 + cb32 * 2 + lo272;
    const uint32_t W1u = smem_u + SM_W1 + cb32 * 2 + lo272;
    const uint32_t Wcu = smem_u + SM_WC1 + cb16 * 2 + lo144;

    const int ecol = (lane & 3) * 2;
    const int erow = lane >> 2;   // row within m-frag for c0/c1 (add mf*16; +8 for c2/c3)

    // ---- one-time staging ----
    stage_weight(W0,  smem, SM_W0,  128, 60,  64,  LDW_B,  tid);
    stage_weight(W1,  smem, SM_W1,  128, 128, 128, LDW_B,  tid);
    stage_weight(Wc1, smem, SM_WC1, 64,  152, 160, LDWC_B, tid);
    if (tid < 192) Wc2t[(tid % 3) * 64 + tid / 3] = Wc2[tid];
    if (tid >= 192 && tid < 256) bc1s[tid - 192] = bc1[tid - 192];
    if (tid < 128) Was[tid] = Wa[tid];
    // zero static pad cols 152..159 of A0 (both halves, 64 rows)
    for (int idx = tid; idx < 2 * 64 * 8; idx += THREADS) {
        int hh = idx >> 9, rr = (idx >> 3) & 63, cc = 152 + (idx & 7);
        *reinterpret_cast<__half*>(smem + SM_A0 + hh * A0_BLK + rr * LDA0_B + cc * 2) = hz;
    }
    __syncthreads();

    const int cnt    = g_cnt;
    const int nTiles = (cnt + 63) >> 6;

    for (int tile = blockIdx.x * 2 + half; tile < nTiles; tile += gridDim.x * 2) {
        const int gi   = (tile << 6) + r;
        const bool live = gi < cnt;

        // ===== S1: pos encode + dir encode (2 threads/sample) =====
        {
            char* rw = smem + a0b + r * LDA0_B;
            float xa = 0.f, xb = 0.f, va = 0.f, vb = 0.f;
            if (live) {
                const float* wp = &g_world[gi * 3];
                const float* vp = &g_vd[gi * 3];
                if (q == 0) { xa = wp[0]; xb = wp[2];         va = vp[0]; vb = vp[2]; }
                else        { xa = wp[1]; xb = wp[2] * 32.f;  va = vp[1]; vb = vp[2] * 4.f; }
            }
            float s, c;
            // primary channel: 10 harmonics
            if (live) sincosf(xa, &s, &c); else { s = 0.f; c = 0.f; }
            {
                int base = q ? 20 : 0;
                #pragma unroll
                for (int j = 0; j < 10; j++) {
                    *reinterpret_cast<__half*>(rw + (base + j) * 2)      = __float2half_rn(s);
                    *reinterpret_cast<__half*>(rw + (base + 10 + j) * 2) = __float2half_rn(c);
                    float ns = 2.f * s * c;
                    float nc = fmaf(-2.f * s, s, 1.f);
                    s = ns; c = nc;
                }
            }
            // channel 2 split: q0 -> j0..4, q1 -> j5..9
            if (live) sincosf(xb, &s, &c); else { s = 0.f; c = 0.f; }
            {
                int base = q ? 45 : 40;
                #pragma unroll
                for (int j = 0; j < 5; j++) {
                    *reinterpret_cast<__half*>(rw + (base + j) * 2)      = __float2half_rn(s);
                    *reinterpret_cast<__half*>(rw + (base + 10 + j) * 2) = __float2half_rn(c);
                    float ns = 2.f * s * c;
                    float nc = fmaf(-2.f * s, s, 1.f);
                    s = ns; c = nc;
                }
            }
            // dir primary: 4 harmonics
            if (live) sincosf(va, &s, &c); else { s = 0.f; c = 0.f; }
            {
                int base = q ? 136 : 128;
                #pragma unroll
                for (int j = 0; j < 4; j++) {
                    *reinterpret_cast<__half*>(rw + (base + j) * 2)     = __float2half_rn(s);
                    *reinterpret_cast<__half*>(rw + (base + 4 + j) * 2) = __float2half_rn(c);
                    float ns = 2.f * s * c;
                    float nc = fmaf(-2.f * s, s, 1.f);
                    s = ns; c = nc;
                }
            }
            // dir channel 2 split: q0 -> j0,1 ; q1 -> j2,3
            if (live) sincosf(vb, &s, &c); else { s = 0.f; c = 0.f; }
            {
                int base = q ? 146 : 144;
                #pragma unroll
                for (int j = 0; j < 2; j++) {
                    *reinterpret_cast<__half*>(rw + (base + j) * 2)     = __float2half_rn(s);
                    *reinterpret_cast<__half*>(rw + (base + 4 + j) * 2) = __float2half_rn(c);
                    float ns = 2.f * s * c;
                    float nc = fmaf(-2.f * s, s, 1.f);
                    s = ns; c = nc;
                }
            }
            // pad cols 60..63 (must rewrite every tile; L1 overwrites them)
            if (q == 1) {
                #pragma unroll
                for (int cc = 60; cc < 64; cc++)
                    *reinterpret_cast<__half*>(rw + cc * 2) = hz;
            }
        }
        HBAR(barid);

        // ===== L0: h0 = relu(enc @ W0 + b0) -> A1 =====
        {
            float acc[4][4][4];
            #pragma unroll
            for (int mf = 0; mf < 4; mf++)
                #pragma unroll
                for (int i = 0; i < 4; i++)
                    #pragma unroll
                    for (int j = 0; j < 4; j++) acc[mf][i][j] = 0.f;
            mma64<4, 2>(A0u, LDA0_B, W0u, LDW_B, acc);
            #pragma unroll
            for (int mf = 0; mf < 4; mf++) {
                int rlo = mf * 16 + erow, rhi = rlo + 8;
                char* dlo = smem + a1b + rlo * LDA1_B;
                char* dhi = smem + a1b + rhi * LDA1_B;
                #pragma unroll
                for (int nf = 0; nf < 4; nf++) {
                    int col = cb32 + nf * 8 + ecol;
                    float2 bv = __ldg(reinterpret_cast<const float2*>(b0 + col));
                    float v0 = fmaxf(acc[mf][nf][0] + bv.x, 0.f);
                    float v1 = fmaxf(acc[mf][nf][1] + bv.y, 0.f);
                    float v2 = fmaxf(acc[mf][nf][2] + bv.x, 0.f);
                    float v3 = fmaxf(acc[mf][nf][3] + bv.y, 0.f);
                    __half2 h01 = __floats2half2_rn(v0, v1);
                    __half2 h23 = __floats2half2_rn(v2, v3);
                    *reinterpret_cast<uint32_t*>(dlo + col * 2) = *reinterpret_cast<uint32_t*>(&h01);
                    *reinterpret_cast<uint32_t*>(dhi + col * 2) = *reinterpret_cast<uint32_t*>(&h23);
                }
            }
        }
        HBAR(barid);

        // ===== L1: h1 = relu(h0 @ W1 + b1) -> A0 cols 0..127; alpha partials =====
        {
            float acc[4][4][4];
            #pragma unroll
            for (int mf = 0; mf < 4; mf++)
                #pragma unroll
                for (int i = 0; i < 4; i++)
                    #pragma unroll
                    for (int j = 0; j < 4; j++) acc[mf][i][j] = 0.f;
            mma64<8, 2>(A1u, LDA1_B, W1u, LDW_B, acc);
            #pragma unroll
            for (int mf = 0; mf < 4; mf++) {
                int rlo = mf * 16 + erow, rhi = rlo + 8;
                char* dlo = smem + a0b + rlo * LDA0_B;
                char* dhi = smem + a0b + rhi * LDA0_B;
                float alo = 0.f, ahi = 0.f;
                #pragma unroll
                for (int nf = 0; nf < 4; nf++) {
                    int col = cb32 + nf * 8 + ecol;
                    float2 bv = __ldg(reinterpret_cast<const float2*>(b1 + col));
                    float2 wv = *reinterpret_cast<const float2*>(Was + col);
                    float v0 = fmaxf(acc[mf][nf][0] + bv.x, 0.f);
                    float v1 = fmaxf(acc[mf][nf][1] + bv.y, 0.f);
                    float v2 = fmaxf(acc[mf][nf][2] + bv.x, 0.f);
                    float v3 = fmaxf(acc[mf][nf][3] + bv.y, 0.f);
                    alo = fmaf(v0, wv.x, alo); alo = fmaf(v1, wv.y, alo);
                    ahi = fmaf(v2, wv.x, ahi); ahi = fmaf(v3, wv.y, ahi);
                    __half2 h01 = __floats2half2_rn(v0, v1);
                    __half2 h23 = __floats2half2_rn(v2, v3);
                    *reinterpret_cast<uint32_t*>(dlo + col * 2) = *reinterpret_cast<uint32_t*>(&h01);
                    *reinterpret_cast<uint32_t*>(dhi + col * 2) = *reinterpret_cast<uint32_t*>(&h23);
                }
                alo += __shfl_xor_sync(0xffffffffu, alo, 1);
                alo += __shfl_xor_sync(0xffffffffu, alo, 2);
                ahi += __shfl_xor_sync(0xffffffffu, ahi, 1);
                ahi += __shfl_xor_sync(0xffffffffu, ahi, 2);
                if ((lane & 3) == 0) {
                    part[rlo * 16 + hw * 4 + 3] = alo;
                    part[rhi * 16 + hw * 4 + 3] = ahi;
                }
            }
        }
        HBAR(barid);

        // ===== Wc1: hc = relu([h1|denc] @ Wc1 + bc1); rgb partials =====
        {
            float acc[4][2][4];
            #pragma unroll
            for (int mf = 0; mf < 4; mf++)
                #pragma unroll
                for (int i = 0; i < 2; i++)
                    #pragma unroll
                    for (int j = 0; j < 4; j++) acc[mf][i][j] = 0.f;
            mma64<10, 1>(A0u, LDA0_B, Wcu, LDWC_B, acc);
            #pragma unroll
            for (int mf = 0; mf < 4; mf++) {
                int rlo = mf * 16 + erow, rhi = rlo + 8;
                float plo[3] = {0.f, 0.f, 0.f}, phi[3] = {0.f, 0.f, 0.f};
                #pragma unroll
                for (int nf = 0; nf < 2; nf++) {
                    int col = cb16 + nf * 8 + ecol;
                    float2 bcv = *reinterpret_cast<const float2*>(bc1s + col);
                    float v0 = fmaxf(acc[mf][nf][0] + bcv.x, 0.f);
                    float v1 = fmaxf(acc[mf][nf][1] + bcv.y, 0.f);
                    float v2 = fmaxf(acc[mf][nf][2] + bcv.x, 0.f);
                    float v3 = fmaxf(acc[mf][nf][3] + bcv.y, 0.f);
                    #pragma unroll
                    for (int j = 0; j < 3; j++) {
                        float2 w = *reinterpret_cast<const float2*>(Wc2t + j * 64 + col);
                        plo[j] = fmaf(v0, w.x, plo[j]); plo[j] = fmaf(v1, w.y, plo[j]);
                        phi[j] = fmaf(v2, w.x, phi[j]); phi[j] = fmaf(v3, w.y, phi[j]);
                    }
                }
                #pragma unroll
                for (int j = 0; j < 3; j++) {
                    plo[j] += __shfl_xor_sync(0xffffffffu, plo[j], 1);
                    plo[j] += __shfl_xor_sync(0xffffffffu, plo[j], 2);
                    phi[j] += __shfl_xor_sync(0xffffffffu, phi[j], 1);
                    phi[j] += __shfl_xor_sync(0xffffffffu, phi[j], 2);
                }
                if ((lane & 3) == 0) {
                    #pragma unroll
                    for (int j = 0; j < 3; j++) {
                        part[rlo * 16 + hw * 4 + j] = plo[j];
                        part[rhi * 16 + hw * 4 + j] = phi[j];
                    }
                }
            }
        }
        HBAR(barid);

        // ===== combine + scatter (64 threads per half) =====
        if (ht < 64) {
            int gi2 = (tile << 6) + ht;
            if (gi2 < cnt) {
                const float* pp = part + ht * 16;
                float r0 = bc20 + pp[0] + pp[4] + pp[8]  + pp[12];
                float r1 = bc21 + pp[1] + pp[5] + pp[9]  + pp[13];
                float r2 = bc22 + pp[2] + pp[6] + pp[10] + pp[14];
                float aa = ba0  + pp[3] + pp[7] + pp[11] + pp[15];
                float4 outv;
                outv.x = 1.0f / (1.0f + __expf(-r0));
                outv.y = 1.0f / (1.0f + __expf(-r1));
                outv.z = 1.0f / (1.0f + __expf(-r2));
                outv.w = 1.0f / (1.0f + __expf(-aa));
                *reinterpret_cast<float4*>(&g_rgba[g_sidx[gi2] * 4]) = outv;
            }
        }
        HBAR(barid);
    }
}

// ---------------- kernel 5: composite (register bitonic sort) ----------------
__global__ void __launch_bounds__(128) k_composite(float* __restrict__ out)
{
    int n = blockIdx.x * blockDim.x + threadIdx.x;
    if (n >= N_RAYS) return;

    float tv[N_PLANES];
    int   pv[N_PLANES];
    #pragma unroll
    for (int p = 0; p < N_PLANES; p++) {
        tv[p] = g_t[p * N_RAYS + n];
        pv[p] = p;
    }

    #pragma unroll
    for (int k = 2; k <= N_PLANES; k <<= 1) {
        #pragma unroll
        for (int j = k >> 1; j > 0; j >>= 1) {
            #pragma unroll
            for (int i = 0; i < N_PLANES; i++) {
                int l = i ^ j;
                if (l > i) {
                    bool up = ((i & k) == 0);
                    bool sw = up ? (tv[i] > tv[l]) : (tv[i] < tv[l]);
                    if (sw) {
                        float tt = tv[i]; tv[i] = tv[l]; tv[l] = tt;
                        int   pp = pv[i]; pv[i] = pv[l]; pv[l] = pp;
                    }
                }
            }
        }
    }

    float trans = 1.0f, sw = 0.0f, depth = 0.0f;
    float c0 = 0.f, c1 = 0.f, c2 = 0.f;
    #pragma unroll
    for (int s = 0; s < N_PLANES; s++) {
        int p = pv[s];
        float4 rg = *reinterpret_cast<const float4*>(&g_rgba[(p * N_RAYS + n) * 4]);
        float a = rg.w;
        float w = a * trans;
        depth = fmaf(tv[s], w, depth);
        c0 = fmaf(rg.x, w, c0);
        c1 = fmaf(rg.y, w, c1);
        c2 = fmaf(rg.z, w, c2);
        sw += w;
        trans *= (1.0f - a);
    }
    float bg = 1.0f - sw;
    out[n * 4 + 0] = c0 + bg;
    out[n * 4 + 1] = c1 + bg;
    out[n * 4 + 2] = c2 + bg;
    out[n * 4 + 3] = depth;
}

// ---------------- launch ----------------
extern "C" void kernel_launch(void* const* d_in, const int* in_sizes, int n_in,
                              void* d_out, int out_size)
{
    const float* ndc    = (const float*)d_in[0];
    const float* campos = (const float*)d_in[1];
    const float* camR   = (const float*)d_in[2];
    const float* basis  = (const float*)d_in[3];
    const float* center = (const float*)d_in[4];
    const float* wh     = (const float*)d_in[5];
    const float* W0     = (const float*)d_in[6];
    const float* b0     = (const float*)d_in[7];
    const float* W1     = (const float*)d_in[8];
    const float* b1     = (const float*)d_in[9];
    const float* Wa     = (const float*)d_in[10];
    const float* ba     = (const float*)d_in[11];
    const float* Wc1    = (const float*)d_in[12];
    const float* bc1    = (const float*)d_in[13];
    const float* Wc2    = (const float*)d_in[14];
    const float* bc2    = (const float*)d_in[15];
    float* out = (float*)d_out;

    static int smem_set = 0;
    if (!smem_set) {
        cudaFuncSetAttribute(k_mlp, cudaFuncAttributeMaxDynamicSharedMemorySize, SMEM_BYTES);
        smem_set = 1;
    }

    k_reset<<<1, 32>>>();
    k_geom<<<NSAMP / 256, 256>>>(ndc, campos, camR, basis, center, wh);
    k_mlp<<<PERSIST_BLOCKS, THREADS, SMEM_BYTES>>>(W0, b0, W1, b1, Wa, ba, Wc1, bc1, Wc2, bc2);
    k_composite<<<(N_RAYS + 127) / 128, 128>>>(out);
}